// round 5
// baseline (speedup 1.0000x reference)
#include <cuda_runtime.h>
#include <cuda_fp16.h>
#include <cstdint>

// ---------------- static scratch ----------------
__device__ __half g_qt[8388608];       // time q  [n][h][c8][w]
__device__ __half g_kt[8388608];       // time k  [n][h][c8][w]
__device__ __half g_qf[8388608];       // freq q  [n][c8][h][w]
__device__ __half g_kf[8388608];       // freq k  [n][c8][h][w]
__device__ __half g_vt[67108864];      // time v  [n][c][h][w]   134 MB
__device__ __half g_vf[67108864];      // freq v  [n][c][h][w]   134 MB
__device__ __half g_tmp[67108864];     // time-pass partial (3x+gt*acc) fp16
__device__ float  g_E[1048576];        // energy fp32 [n][512][512]
__device__ __half g_attn[1048576];     // attn fp16
__device__ __half g_wpack[10240];      // [160][64]: tq,tk,fq,fk,tv,fv
__device__ float  g_bpack[160];

// ---------------- helpers ----------------
__device__ __forceinline__ uint32_t smem_u32(const void* p) {
    return (uint32_t)__cvta_generic_to_shared(p);
}
__device__ __forceinline__ void cp16(uint32_t dst, const void* src) {
    asm volatile("cp.async.cg.shared.global [%0], [%1], 16;" :: "r"(dst), "l"(src));
}
__device__ __forceinline__ void cp_commit() {
    asm volatile("cp.async.commit_group;");
}
__device__ __forceinline__ void ldm_x4(uint32_t addr, uint32_t& r0, uint32_t& r1, uint32_t& r2, uint32_t& r3) {
    asm volatile("ldmatrix.sync.aligned.m8n8.x4.shared.b16 {%0,%1,%2,%3}, [%4];"
                 : "=r"(r0), "=r"(r1), "=r"(r2), "=r"(r3) : "r"(addr));
}
__device__ __forceinline__ void ldm_x4t(uint32_t addr, uint32_t& r0, uint32_t& r1, uint32_t& r2, uint32_t& r3) {
    asm volatile("ldmatrix.sync.aligned.m8n8.x4.trans.shared.b16 {%0,%1,%2,%3}, [%4];"
                 : "=r"(r0), "=r"(r1), "=r"(r2), "=r"(r3) : "r"(addr));
}
__device__ __forceinline__ void mma16816(float* c, const uint32_t* a, const uint32_t* b) {
    asm volatile("mma.sync.aligned.m16n8k16.row.col.f32.f16.f16.f32 "
                 "{%0,%1,%2,%3},{%4,%5,%6,%7},{%8,%9},{%0,%1,%2,%3};"
                 : "+f"(c[0]), "+f"(c[1]), "+f"(c[2]), "+f"(c[3])
                 : "r"(a[0]), "r"(a[1]), "r"(a[2]), "r"(a[3]), "r"(b[0]), "r"(b[1]));
}

// ---------------- weight packing ----------------
__global__ void k_pack_w(
    const float* __restrict__ tqw, const float* __restrict__ tkw,
    const float* __restrict__ fqw, const float* __restrict__ fkw,
    const float* __restrict__ tqb, const float* __restrict__ tkb,
    const float* __restrict__ fqb, const float* __restrict__ fkb,
    const float* __restrict__ tvw, const float* __restrict__ fvw,
    const float* __restrict__ tvb, const float* __restrict__ fvb)
{
    int t = threadIdx.x;   // 256
    for (int i = t; i < 512; i += 256) {
        g_wpack[i]        = __float2half(tqw[i]);
        g_wpack[512 + i]  = __float2half(tkw[i]);
        g_wpack[1024 + i] = __float2half(fqw[i]);
        g_wpack[1536 + i] = __float2half(fkw[i]);
    }
    for (int i = t; i < 4096; i += 256) {
        g_wpack[2048 + i] = __float2half(tvw[i]);
        g_wpack[6144 + i] = __float2half(fvw[i]);
    }
    if (t < 8) {
        g_bpack[t] = tqb[t]; g_bpack[8 + t] = tkb[t];
        g_bpack[16 + t] = fqb[t]; g_bpack[24 + t] = fkb[t];
    }
    if (t < 64) { g_bpack[32 + t] = tvb[t]; g_bpack[96 + t] = fvb[t]; }
}

// ---------------- fused projection: x fp32 -> q/k (both passes) + v (both passes) ----------------
// Each block: 128 consecutive pixels (within one (n,h) row). M=160 stacked outputs.
__global__ __launch_bounds__(256) void k_proj(const float* __restrict__ x)
{
    __shared__ __align__(16) __half Ws[160][72];
    __shared__ __align__(16) __half Xs[64][136];
    __shared__ float Bb[160];

    const int tid = threadIdx.x;
    const int warp = tid >> 5, lane = tid & 31;
    const int wm = warp >> 2, wn = warp & 3;       // 2 x 4 warps
    const int tr = lane & 7, tg = lane >> 3;

    const int nb = blockIdx.x >> 11;               // 2048 chunks per n
    const int chunk = blockIdx.x & 2047;
    const long long pix0 = (long long)chunk * 128;
    const int h = (int)(pix0 >> 9);
    const int w0 = (int)(pix0 & 511);

    // weights via cp.async
    uint32_t wS = smem_u32(&Ws[0][0]);
    for (int c = tid; c < 1280; c += 256) {
        int r = c >> 3, s = (c & 7) * 8;
        cp16(wS + (uint32_t)((r * 72 + s) * 2), g_wpack + r * 64 + s);
    }
    cp_commit();
    if (tid < 160) Bb[tid] = g_bpack[tid];

    // x tile load + fp16 convert: 64 channels x 128 px
    const float4* x4 = reinterpret_cast<const float4*>(x) + (long long)nb * 4194304 + (pix0 >> 2);
    for (int i = tid; i < 2048; i += 256) {
        int c = i >> 5, f4 = i & 31;
        float4 f = x4[(long long)c * 65536 + f4];
        *reinterpret_cast<__half2*>(&Xs[c][f4 * 4])     = __floats2half2_rn(f.x, f.y);
        *reinterpret_cast<__half2*>(&Xs[c][f4 * 4 + 2]) = __floats2half2_rn(f.z, f.w);
    }
    asm volatile("cp.async.wait_group 0;" ::: "memory");
    __syncthreads();

    uint32_t xS = smem_u32(&Xs[0][0]);
    float acc[5][4][4];
#pragma unroll
    for (int mi = 0; mi < 5; mi++)
#pragma unroll
        for (int ni = 0; ni < 4; ni++)
#pragma unroll
            for (int j = 0; j < 4; j++) acc[mi][ni][j] = 0.f;

#pragma unroll
    for (int ks = 0; ks < 4; ks++) {
        const int k0 = ks * 16;
        uint32_t a[5][4];
#pragma unroll
        for (int mi = 0; mi < 5; mi++) {
            int row = wm * 80 + mi * 16 + tr + (tg & 1) * 8;
            int col = k0 + (tg >> 1) * 8;
            ldm_x4(wS + (uint32_t)((row * 72 + col) * 2), a[mi][0], a[mi][1], a[mi][2], a[mi][3]);
        }
        uint32_t b[4][2];
#pragma unroll
        for (int np = 0; np < 2; np++) {
            int row = k0 + tr + (tg & 1) * 8;
            int col = wn * 32 + np * 16 + (tg >> 1) * 8;
            uint32_t q0, q1, q2, q3;
            ldm_x4t(xS + (uint32_t)((row * 136 + col) * 2), q0, q1, q2, q3);
            b[np * 2][0] = q0; b[np * 2][1] = q1;
            b[np * 2 + 1][0] = q2; b[np * 2 + 1][1] = q3;
        }
#pragma unroll
        for (int mi = 0; mi < 5; mi++)
#pragma unroll
            for (int ni = 0; ni < 4; ni++)
                mma16816(acc[mi][ni], a[mi], b[ni]);
    }

    // scatter epilogue
#pragma unroll
    for (int mi = 0; mi < 5; mi++) {
#pragma unroll
        for (int ni = 0; ni < 4; ni++) {
            int lc = wn * 32 + ni * 8 + (lane & 3) * 2;
#pragma unroll
            for (int hf = 0; hf < 2; hf++) {
                int r = wm * 80 + mi * 16 + (lane >> 2) + hf * 8;
                float bv = Bb[r];
                __half2 hv = __floats2half2_rn(acc[mi][ni][hf * 2] + bv,
                                               acc[mi][ni][hf * 2 + 1] + bv);
                __half* dst;
                if (r < 32) {
                    int kind = r >> 3;
                    __half* base = kind == 0 ? g_qt : kind == 1 ? g_kt : kind == 2 ? g_qf : g_kf;
                    long long o = (long long)nb * 2097152;
                    if (kind < 2) dst = base + o + (long long)h * 4096 + (r & 7) * 512 + w0 + lc;
                    else          dst = base + o + (long long)(r & 7) * 262144 + pix0 + lc;
                } else {
                    int r2 = r - 32;
                    __half* base = (r2 < 64) ? g_vt : g_vf;
                    int cc = (r2 < 64) ? r2 : r2 - 64;
                    dst = base + (long long)nb * 16777216 + (long long)cc * 262144 + pix0 + lc;
                }
                *reinterpret_cast<__half2*>(dst) = hv;
            }
        }
    }
}

// ---------------- softmax over rows of 512 ----------------
__global__ __launch_bounds__(256) void k_softmax() {
    int r = blockIdx.x, t = threadIdx.x;
    const float* e = g_E + (long long)r * 512;
    float v0 = e[t], v1 = e[t + 256];

    __shared__ float red[8];
    float m = fmaxf(v0, v1);
#pragma unroll
    for (int o = 16; o; o >>= 1) m = fmaxf(m, __shfl_xor_sync(0xffffffffu, m, o));
    if ((t & 31) == 0) red[t >> 5] = m;
    __syncthreads();
    float M = red[0];
#pragma unroll
    for (int i = 1; i < 8; i++) M = fmaxf(M, red[i]);
    __syncthreads();

    float e0 = __expf(v0 - M), e1 = __expf(v1 - M);
    float s = e0 + e1;
#pragma unroll
    for (int o = 16; o; o >>= 1) s += __shfl_xor_sync(0xffffffffu, s, o);
    if ((t & 31) == 0) red[t >> 5] = s;
    __syncthreads();
    float S = 0.f;
#pragma unroll
    for (int i = 0; i < 8; i++) S += red[i];
    float inv = 1.f / S;

    __half* a = g_attn + (long long)r * 512;
    a[t] = __float2half(e0 * inv);
    a[t + 256] = __float2half(e1 * inv);
}

// ---------------- generic fp16 tensor-core GEMM, 3-stage cp.async ----------------
// OPA: 0 -> A[m][k], 1 -> A[k][m].   OPB: 0 -> B[k][n], 1 -> B[n][k].
// EPI: 0 Cf=acc | 6 tmp_half = 3*Xin + g*acc | 7 Cf = tmp_half + g*acc
// BMODE: 0 -> offA=z*bsA | 1 -> offA=(z>>6)*bsA
template<int BM, int BN, int BK, int OPA, int OPB, int EPI, int BMODE, int S>
__global__ __launch_bounds__(256) void k_gemm(
    const __half* __restrict__ Ag, const __half* __restrict__ Bg,
    float* __restrict__ Cf, __half* __restrict__ Th,
    const float* __restrict__ gam, const float* __restrict__ Xin,
    int K, int lda, int ldb, int ldc,
    long long bsA, long long bsB, long long bsC)
{
    constexpr int WM_ = BM / 32;
    constexpr int WNT = BN / (8 / WM_);
    constexpr int NF = WNT / 8;
    constexpr int KS = BK / 16;
    constexpr int AROWS = OPA ? BK : BM;
    constexpr int ACOLS = (OPA ? BM : BK) + 8;
    constexpr int BROWS = OPB ? BN : BK;
    constexpr int BCOLS = (OPB ? BK : BN) + 8;

    extern __shared__ __align__(16) char dsm[];
    uint32_t aS = smem_u32(dsm);
    uint32_t bS = aS + (uint32_t)(S * AROWS * ACOLS * 2);

    const int tid = threadIdx.x;
    const int warp = tid >> 5, lane = tid & 31;
    const int wm = warp % WM_, wn = warp / WM_;
    const int tr = lane & 7, tg = lane >> 3;

    const int z = blockIdx.z;
    const int n_base = blockIdx.x * BN;
    const int m_base = blockIdx.y * BM;

    long long offA = (BMODE == 1 ? (long long)(z >> 6) : (long long)z) * bsA;
    const __half* Ab = Ag + offA + (OPA ? (long long)m_base : (long long)m_base * lda);
    const __half* Bb = Bg + (long long)z * bsB + (OPB ? (long long)n_base * ldb : (long long)n_base);

    const int KT = K / BK;

    auto load_tile = [&](int st, int kt) {
        {
            constexpr int CH = (OPA ? BM : BK) / 8;
            constexpr int TOT = AROWS * CH;
#pragma unroll
            for (int c0 = 0; c0 < TOT; c0 += 256) {
                int c = c0 + tid;
                int r = c / CH, s = (c % CH) * 8;
                const __half* src = OPA ? (Ab + (long long)(kt * BK + r) * lda + s)
                                        : (Ab + (long long)r * lda + kt * BK + s);
                cp16(aS + (uint32_t)(((st * AROWS + r) * ACOLS + s) * 2), src);
            }
        }
        {
            constexpr int CH = (OPB ? BK : BN) / 8;
            constexpr int TOT = BROWS * CH;
#pragma unroll
            for (int c0 = 0; c0 < TOT; c0 += 256) {
                int c = c0 + tid;
                int r = c / CH, s = (c % CH) * 8;
                const __half* src = OPB ? (Bb + (long long)r * ldb + kt * BK + s)
                                        : (Bb + (long long)(kt * BK + r) * ldb + s);
                cp16(bS + (uint32_t)(((st * BROWS + r) * BCOLS + s) * 2), src);
            }
        }
        cp_commit();
    };

    float acc[2][NF][4];
#pragma unroll
    for (int mi = 0; mi < 2; mi++)
#pragma unroll
        for (int ni = 0; ni < NF; ni++)
#pragma unroll
            for (int j = 0; j < 4; j++) acc[mi][ni][j] = 0.f;

#pragma unroll
    for (int s = 0; s < S - 1; s++) load_tile(s, s);   // requires KT >= S-1

    for (int kt = 0; kt < KT; kt++) {
        asm volatile("cp.async.wait_group %0;" :: "n"(S - 2) : "memory");
        __syncthreads();

        int nk = kt + S - 1;
        if (nk < KT) load_tile(nk % S, nk);
        else cp_commit();

        const int st = kt % S;
#pragma unroll
        for (int ks = 0; ks < KS; ks++) {
            const int k0 = ks * 16;
            uint32_t a[2][4];
#pragma unroll
            for (int mi = 0; mi < 2; mi++) {
                int r0 = wm * 32 + mi * 16;
                if (OPA == 0) {
                    int row = r0 + tr + (tg & 1) * 8, col = k0 + (tg >> 1) * 8;
                    ldm_x4(aS + (uint32_t)(((st * AROWS + row) * ACOLS + col) * 2),
                           a[mi][0], a[mi][1], a[mi][2], a[mi][3]);
                } else {
                    int row = k0 + tr + (tg >> 1) * 8, col = r0 + (tg & 1) * 8;
                    ldm_x4t(aS + (uint32_t)(((st * AROWS + row) * ACOLS + col) * 2),
                            a[mi][0], a[mi][1], a[mi][2], a[mi][3]);
                }
            }
            uint32_t b[NF][2];
#pragma unroll
            for (int np = 0; np < NF / 2; np++) {
                int c0 = wn * WNT + np * 16;
                uint32_t q0, q1, q2, q3;
                if (OPB == 0) {
                    int row = k0 + tr + (tg & 1) * 8, col = c0 + (tg >> 1) * 8;
                    ldm_x4t(bS + (uint32_t)(((st * BROWS + row) * BCOLS + col) * 2), q0, q1, q2, q3);
                } else {
                    int row = c0 + tr + (tg >> 1) * 8, col = k0 + (tg & 1) * 8;
                    ldm_x4(bS + (uint32_t)(((st * BROWS + row) * BCOLS + col) * 2), q0, q1, q2, q3);
                }
                b[np * 2][0] = q0; b[np * 2][1] = q1;
                b[np * 2 + 1][0] = q2; b[np * 2 + 1][1] = q3;
            }
#pragma unroll
            for (int mi = 0; mi < 2; mi++)
#pragma unroll
                for (int ni = 0; ni < NF; ni++)
                    mma16816(acc[mi][ni], a[mi], b[ni]);
        }
        __syncthreads();
    }

    // ---------------- epilogue ----------------
    const float g = (EPI == 6 || EPI == 7) ? gam[0] : 0.f;
#pragma unroll
    for (int mi = 0; mi < 2; mi++) {
#pragma unroll
        for (int ni = 0; ni < NF; ni++) {
            int lr0 = wm * 32 + mi * 16 + (lane >> 2);
            int lc = wn * WNT + ni * 8 + (lane & 3) * 2;
            float* ac = acc[mi][ni];
#pragma unroll
            for (int hf = 0; hf < 2; hf++) {
                int r = lr0 + hf * 8;
                float v0 = ac[hf * 2 + 0], v1 = ac[hf * 2 + 1];
                long long idx = (long long)z * bsC + (long long)(m_base + r) * ldc + n_base + lc;
                if constexpr (EPI == 0) {
                    *reinterpret_cast<float2*>(Cf + idx) = make_float2(v0, v1);
                } else if constexpr (EPI == 6) {
                    float2 xv = *reinterpret_cast<const float2*>(Xin + idx);
                    *reinterpret_cast<__half2*>(Th + idx) =
                        __floats2half2_rn(3.f * xv.x + g * v0, 3.f * xv.y + g * v1);
                } else if constexpr (EPI == 7) {
                    __half2 tv = *reinterpret_cast<const __half2*>(Th + idx);
                    *reinterpret_cast<float2*>(Cf + idx) =
                        make_float2(__half2float(tv.x) + g * v0, __half2float(tv.y) + g * v1);
                }
            }
        }
    }
}

// ---------------- host launcher ----------------
template<int BM, int BN, int BK, int OPA, int OPB, int EPI, int BMODE, int S = 3>
static void launch_gemm(dim3 grid,
    const __half* A, const __half* B, float* Cf, __half* Th,
    const float* gam, const float* Xin,
    int K, int lda, int ldb, int ldc, long long bsA, long long bsB, long long bsC)
{
    constexpr int AR = OPA ? BK : BM, AC = (OPA ? BM : BK) + 8;
    constexpr int BR = OPB ? BN : BK, BC = (OPB ? BK : BN) + 8;
    constexpr int sz = 2 * S * (AR * AC + BR * BC);
    auto kfn = k_gemm<BM, BN, BK, OPA, OPB, EPI, BMODE, S>;
    cudaFuncSetAttribute(kfn, cudaFuncAttributeMaxDynamicSharedMemorySize, sz);
    kfn<<<grid, 256, sz>>>(A, B, Cf, Th, gam, Xin, K, lda, ldb, ldc, bsA, bsB, bsC);
}

extern "C" void kernel_launch(void* const* d_in, const int* in_sizes, int n_in,
                              void* d_out, int out_size)
{
    const float* x    = (const float*)d_in[0];
    const float* tq_w = (const float*)d_in[1];
    const float* tq_b = (const float*)d_in[2];
    const float* tk_w = (const float*)d_in[3];
    const float* tk_b = (const float*)d_in[4];
    const float* tv_w = (const float*)d_in[5];
    const float* tv_b = (const float*)d_in[6];
    const float* t_g  = (const float*)d_in[7];
    const float* fq_w = (const float*)d_in[8];
    const float* fq_b = (const float*)d_in[9];
    const float* fk_w = (const float*)d_in[10];
    const float* fk_b = (const float*)d_in[11];
    const float* fv_w = (const float*)d_in[12];
    const float* fv_b = (const float*)d_in[13];
    const float* f_g  = (const float*)d_in[14];
    float* out = (float*)d_out;

    __half *qt, *kt, *qf, *kf, *vt, *vf, *tmp, *attn;
    float* E;
    cudaGetSymbolAddress((void**)&qt, g_qt);
    cudaGetSymbolAddress((void**)&kt, g_kt);
    cudaGetSymbolAddress((void**)&qf, g_qf);
    cudaGetSymbolAddress((void**)&kf, g_kf);
    cudaGetSymbolAddress((void**)&vt, g_vt);
    cudaGetSymbolAddress((void**)&vf, g_vf);
    cudaGetSymbolAddress((void**)&tmp, g_tmp);
    cudaGetSymbolAddress((void**)&attn, g_attn);
    cudaGetSymbolAddress((void**)&E, g_E);

    k_pack_w<<<1, 256>>>(tq_w, tk_w, fq_w, fk_w, tq_b, tk_b, fq_b, fk_b,
                         tv_w, fv_w, tv_b, fv_b);

    // fused projection: all q/k/v for both passes, reading x fp32 directly
    k_proj<<<8192, 256>>>(x);

    // ---- time attention ----
    launch_gemm<128, 64, 64, 0, 1, 0, 0>(dim3(8, 4, 4),
        qt, kt, E, nullptr, nullptr, nullptr,
        4096, 4096, 4096, 512, 2097152LL, 2097152LL, 262144LL);
    k_softmax<<<2048, 256>>>();
    // tmp = 3x + gt * attn@v   (fp16), batch z=(n,c)
    launch_gemm<128, 128, 64, 0, 0, 6, 1>(dim3(4, 4, 256),
        attn, vt, nullptr, tmp, t_g, x,
        512, 512, 512, 512, 262144LL, 262144LL, 262144LL);

    // ---- freq attention ----
    launch_gemm<128, 64, 64, 1, 0, 0, 0>(dim3(8, 4, 4),
        qf, kf, E, nullptr, nullptr, nullptr,
        4096, 512, 512, 512, 2097152LL, 2097152LL, 262144LL);
    k_softmax<<<2048, 256>>>();
    // out = tmp + gf * v@attn^T   (fp32), per n
    launch_gemm<128, 128, 64, 0, 1, 7, 0>(dim3(4, 256, 4),
        vf, attn, out, tmp, f_g, nullptr,
        512, 512, 512, 512, 16777216LL, 262144LL, 16777216LL);
}

// round 6
// speedup vs baseline: 1.1106x; 1.1106x over previous
#include <cuda_runtime.h>
#include <cuda_fp16.h>
#include <cstdint>

// ---------------- static scratch ----------------
__device__ __half g_qt[8388608];       // time q  [n][h][c8][w]
__device__ __half g_kt[8388608];       // time k  [n][h][c8][w]
__device__ __half g_qf[8388608];       // freq q  [n][c8][h][w]
__device__ __half g_kf[8388608];       // freq k  [n][c8][h][w]
__device__ __half g_vt[67108864];      // time v  [n][c][h][w]   134 MB
__device__ __half g_vf[67108864];      // freq v  [n][c][h][w]   134 MB
__device__ __half g_tmp[67108864];     // time-pass partial (3x+gt*acc) fp16
__device__ float  g_E[1048576];        // energy fp32 [n][512][512]
__device__ __half g_attn[1048576];     // attn fp16
__device__ __half g_wpack[10240];      // [160][64]: tq,tk,fq,fk,tv,fv
__device__ float  g_bpack[160];

// ---------------- helpers ----------------
__device__ __forceinline__ uint32_t smem_u32(const void* p) {
    return (uint32_t)__cvta_generic_to_shared(p);
}
__device__ __forceinline__ void cp16(uint32_t dst, const void* src) {
    asm volatile("cp.async.cg.shared.global [%0], [%1], 16;" :: "r"(dst), "l"(src));
}
__device__ __forceinline__ void cp_commit() {
    asm volatile("cp.async.commit_group;");
}
__device__ __forceinline__ void ldm_x4(uint32_t addr, uint32_t& r0, uint32_t& r1, uint32_t& r2, uint32_t& r3) {
    asm volatile("ldmatrix.sync.aligned.m8n8.x4.shared.b16 {%0,%1,%2,%3}, [%4];"
                 : "=r"(r0), "=r"(r1), "=r"(r2), "=r"(r3) : "r"(addr));
}
__device__ __forceinline__ void ldm_x4t(uint32_t addr, uint32_t& r0, uint32_t& r1, uint32_t& r2, uint32_t& r3) {
    asm volatile("ldmatrix.sync.aligned.m8n8.x4.trans.shared.b16 {%0,%1,%2,%3}, [%4];"
                 : "=r"(r0), "=r"(r1), "=r"(r2), "=r"(r3) : "r"(addr));
}
__device__ __forceinline__ void mma16816(float* c, const uint32_t* a, const uint32_t* b) {
    asm volatile("mma.sync.aligned.m16n8k16.row.col.f32.f16.f16.f32 "
                 "{%0,%1,%2,%3},{%4,%5,%6,%7},{%8,%9},{%0,%1,%2,%3};"
                 : "+f"(c[0]), "+f"(c[1]), "+f"(c[2]), "+f"(c[3])
                 : "r"(a[0]), "r"(a[1]), "r"(a[2]), "r"(a[3]), "r"(b[0]), "r"(b[1]));
}

// ---------------- weight packing ----------------
__global__ void k_pack_w(
    const float* __restrict__ tqw, const float* __restrict__ tkw,
    const float* __restrict__ fqw, const float* __restrict__ fkw,
    const float* __restrict__ tqb, const float* __restrict__ tkb,
    const float* __restrict__ fqb, const float* __restrict__ fkb,
    const float* __restrict__ tvw, const float* __restrict__ fvw,
    const float* __restrict__ tvb, const float* __restrict__ fvb)
{
    int t = threadIdx.x;   // 256
    for (int i = t; i < 512; i += 256) {
        g_wpack[i]        = __float2half(tqw[i]);
        g_wpack[512 + i]  = __float2half(tkw[i]);
        g_wpack[1024 + i] = __float2half(fqw[i]);
        g_wpack[1536 + i] = __float2half(fkw[i]);
    }
    for (int i = t; i < 4096; i += 256) {
        g_wpack[2048 + i] = __float2half(tvw[i]);
        g_wpack[6144 + i] = __float2half(fvw[i]);
    }
    if (t < 8) {
        g_bpack[t] = tqb[t]; g_bpack[8 + t] = tkb[t];
        g_bpack[16 + t] = fqb[t]; g_bpack[24 + t] = fkb[t];
    }
    if (t < 64) { g_bpack[32 + t] = tvb[t]; g_bpack[96 + t] = fvb[t]; }
}

// ---------------- fused projection: x fp32 -> q/k (both passes) + v (both passes) ----------------
// Each block: 128 consecutive pixels (within one (n,h) row). M=160 stacked outputs.
__global__ __launch_bounds__(256) void k_proj(const float* __restrict__ x)
{
    __shared__ __align__(16) __half Ws[160][72];
    __shared__ __align__(16) __half Xs[64][136];
    __shared__ float Bb[160];

    const int tid = threadIdx.x;
    const int warp = tid >> 5, lane = tid & 31;
    const int wm = warp >> 2, wn = warp & 3;       // 2 x 4 warps
    const int tr = lane & 7, tg = lane >> 3;

    const int nb = blockIdx.x >> 11;               // 2048 chunks per n
    const int chunk = blockIdx.x & 2047;
    const long long pix0 = (long long)chunk * 128;
    const int h = (int)(pix0 >> 9);
    const int w0 = (int)(pix0 & 511);

    // weights via cp.async
    uint32_t wS = smem_u32(&Ws[0][0]);
    for (int c = tid; c < 1280; c += 256) {
        int r = c >> 3, s = (c & 7) * 8;
        cp16(wS + (uint32_t)((r * 72 + s) * 2), g_wpack + r * 64 + s);
    }
    cp_commit();
    if (tid < 160) Bb[tid] = g_bpack[tid];

    // x tile load + fp16 convert: 64 channels x 128 px
    const float4* x4 = reinterpret_cast<const float4*>(x) + (long long)nb * 4194304 + (pix0 >> 2);
    for (int i = tid; i < 2048; i += 256) {
        int c = i >> 5, f4 = i & 31;
        float4 f = x4[(long long)c * 65536 + f4];
        *reinterpret_cast<__half2*>(&Xs[c][f4 * 4])     = __floats2half2_rn(f.x, f.y);
        *reinterpret_cast<__half2*>(&Xs[c][f4 * 4 + 2]) = __floats2half2_rn(f.z, f.w);
    }
    asm volatile("cp.async.wait_group 0;" ::: "memory");
    __syncthreads();

    uint32_t xS = smem_u32(&Xs[0][0]);
    float acc[5][4][4];
#pragma unroll
    for (int mi = 0; mi < 5; mi++)
#pragma unroll
        for (int ni = 0; ni < 4; ni++)
#pragma unroll
            for (int j = 0; j < 4; j++) acc[mi][ni][j] = 0.f;

#pragma unroll
    for (int ks = 0; ks < 4; ks++) {
        const int k0 = ks * 16;
        uint32_t a[5][4];
#pragma unroll
        for (int mi = 0; mi < 5; mi++) {
            int row = wm * 80 + mi * 16 + tr + (tg & 1) * 8;
            int col = k0 + (tg >> 1) * 8;
            ldm_x4(wS + (uint32_t)((row * 72 + col) * 2), a[mi][0], a[mi][1], a[mi][2], a[mi][3]);
        }
        uint32_t b[4][2];
#pragma unroll
        for (int np = 0; np < 2; np++) {
            int row = k0 + tr + (tg & 1) * 8;
            int col = wn * 32 + np * 16 + (tg >> 1) * 8;
            uint32_t q0, q1, q2, q3;
            ldm_x4t(xS + (uint32_t)((row * 136 + col) * 2), q0, q1, q2, q3);
            b[np * 2][0] = q0; b[np * 2][1] = q1;
            b[np * 2 + 1][0] = q2; b[np * 2 + 1][1] = q3;
        }
#pragma unroll
        for (int mi = 0; mi < 5; mi++)
#pragma unroll
            for (int ni = 0; ni < 4; ni++)
                mma16816(acc[mi][ni], a[mi], b[ni]);
    }

    // scatter epilogue
#pragma unroll
    for (int mi = 0; mi < 5; mi++) {
#pragma unroll
        for (int ni = 0; ni < 4; ni++) {
            int lc = wn * 32 + ni * 8 + (lane & 3) * 2;
#pragma unroll
            for (int hf = 0; hf < 2; hf++) {
                int r = wm * 80 + mi * 16 + (lane >> 2) + hf * 8;
                float bv = Bb[r];
                __half2 hv = __floats2half2_rn(acc[mi][ni][hf * 2] + bv,
                                               acc[mi][ni][hf * 2 + 1] + bv);
                __half* dst;
                if (r < 32) {
                    int kind = r >> 3;
                    __half* base = kind == 0 ? g_qt : kind == 1 ? g_kt : kind == 2 ? g_qf : g_kf;
                    long long o = (long long)nb * 2097152;
                    if (kind < 2) dst = base + o + (long long)h * 4096 + (r & 7) * 512 + w0 + lc;
                    else          dst = base + o + (long long)(r & 7) * 262144 + pix0 + lc;
                } else {
                    int r2 = r - 32;
                    __half* base = (r2 < 64) ? g_vt : g_vf;
                    int cc = (r2 < 64) ? r2 : r2 - 64;
                    dst = base + (long long)nb * 16777216 + (long long)cc * 262144 + pix0 + lc;
                }
                *reinterpret_cast<__half2*>(dst) = hv;
            }
        }
    }
}

// ---------------- softmax over rows of 512 ----------------
__global__ __launch_bounds__(256) void k_softmax() {
    int r = blockIdx.x, t = threadIdx.x;
    const float* e = g_E + (long long)r * 512;
    float v0 = e[t], v1 = e[t + 256];

    __shared__ float red[8];
    float m = fmaxf(v0, v1);
#pragma unroll
    for (int o = 16; o; o >>= 1) m = fmaxf(m, __shfl_xor_sync(0xffffffffu, m, o));
    if ((t & 31) == 0) red[t >> 5] = m;
    __syncthreads();
    float M = red[0];
#pragma unroll
    for (int i = 1; i < 8; i++) M = fmaxf(M, red[i]);
    __syncthreads();

    float e0 = __expf(v0 - M), e1 = __expf(v1 - M);
    float s = e0 + e1;
#pragma unroll
    for (int o = 16; o; o >>= 1) s += __shfl_xor_sync(0xffffffffu, s, o);
    if ((t & 31) == 0) red[t >> 5] = s;
    __syncthreads();
    float S = 0.f;
#pragma unroll
    for (int i = 0; i < 8; i++) S += red[i];
    float inv = 1.f / S;

    __half* a = g_attn + (long long)r * 512;
    a[t] = __float2half(e0 * inv);
    a[t + 256] = __float2half(e1 * inv);
}

// ---------------- generic fp16 tensor-core GEMM, 2-stage cp.async (proven R2 mainloop) ----------------
// OPA: 0 -> A[m][k], 1 -> A[k][m].   OPB: 0 -> B[k][n], 1 -> B[n][k].
// EPI: 0 Cf=acc | 6 tmp_half = 3*Xin + g*acc | 7 Cf = tmp_half + g*acc
// BMODE: 0 -> offA=z*bsA | 1 -> offA=(z>>6)*bsA
template<int BM, int BN, int BK, int OPA, int OPB, int EPI, int BMODE>
__global__ __launch_bounds__(256) void k_gemm(
    const __half* __restrict__ Ag, const __half* __restrict__ Bg,
    float* __restrict__ Cf, __half* __restrict__ Th,
    const float* __restrict__ gam, const float* __restrict__ Xin,
    int K, int lda, int ldb, int ldc,
    long long bsA, long long bsB, long long bsC)
{
    constexpr int WM_ = BM / 32;
    constexpr int WNT = BN / (8 / WM_);
    constexpr int NF = WNT / 8;
    constexpr int KS = BK / 16;
    constexpr int AROWS = OPA ? BK : BM;
    constexpr int ACOLS = (OPA ? BM : BK) + 8;
    constexpr int BROWS = OPB ? BN : BK;
    constexpr int BCOLS = (OPB ? BK : BN) + 8;

    extern __shared__ __align__(16) char dsm[];
    uint32_t aS = smem_u32(dsm);
    uint32_t bS = aS + (uint32_t)(2 * AROWS * ACOLS * 2);

    const int tid = threadIdx.x;
    const int warp = tid >> 5, lane = tid & 31;
    const int wm = warp % WM_, wn = warp / WM_;
    const int tr = lane & 7, tg = lane >> 3;

    const int z = blockIdx.z;
    const int n_base = blockIdx.x * BN;
    const int m_base = blockIdx.y * BM;

    long long offA = (BMODE == 1 ? (long long)(z >> 6) : (long long)z) * bsA;
    const __half* Ab = Ag + offA + (OPA ? (long long)m_base : (long long)m_base * lda);
    const __half* Bb = Bg + (long long)z * bsB + (OPB ? (long long)n_base * ldb : (long long)n_base);

    const int KT = K / BK;

    auto load_tile = [&](int st, int kt) {
        {
            constexpr int CH = (OPA ? BM : BK) / 8;
            constexpr int TOT = AROWS * CH;
#pragma unroll
            for (int c0 = 0; c0 < TOT; c0 += 256) {
                int c = c0 + tid;
                int r = c / CH, s = (c % CH) * 8;
                const __half* src = OPA ? (Ab + (long long)(kt * BK + r) * lda + s)
                                        : (Ab + (long long)r * lda + kt * BK + s);
                cp16(aS + (uint32_t)(((st * AROWS + r) * ACOLS + s) * 2), src);
            }
        }
        {
            constexpr int CH = (OPB ? BK : BN) / 8;
            constexpr int TOT = BROWS * CH;
#pragma unroll
            for (int c0 = 0; c0 < TOT; c0 += 256) {
                int c = c0 + tid;
                int r = c / CH, s = (c % CH) * 8;
                const __half* src = OPB ? (Bb + (long long)r * ldb + kt * BK + s)
                                        : (Bb + (long long)(kt * BK + r) * ldb + s);
                cp16(bS + (uint32_t)(((st * BROWS + r) * BCOLS + s) * 2), src);
            }
        }
        cp_commit();
    };

    float acc[2][NF][4];
#pragma unroll
    for (int mi = 0; mi < 2; mi++)
#pragma unroll
        for (int ni = 0; ni < NF; ni++)
#pragma unroll
            for (int j = 0; j < 4; j++) acc[mi][ni][j] = 0.f;

    load_tile(0, 0);

    for (int kt = 0; kt < KT; kt++) {
        if (kt + 1 < KT) {
            load_tile((kt + 1) & 1, kt + 1);
            asm volatile("cp.async.wait_group 1;" ::: "memory");
        } else {
            asm volatile("cp.async.wait_group 0;" ::: "memory");
        }
        __syncthreads();

        const int st = kt & 1;
#pragma unroll
        for (int ks = 0; ks < KS; ks++) {
            const int k0 = ks * 16;
            uint32_t a[2][4];
#pragma unroll
            for (int mi = 0; mi < 2; mi++) {
                int r0 = wm * 32 + mi * 16;
                if (OPA == 0) {
                    int row = r0 + tr + (tg & 1) * 8, col = k0 + (tg >> 1) * 8;
                    ldm_x4(aS + (uint32_t)(((st * AROWS + row) * ACOLS + col) * 2),
                           a[mi][0], a[mi][1], a[mi][2], a[mi][3]);
                } else {
                    int row = k0 + tr + (tg >> 1) * 8, col = r0 + (tg & 1) * 8;
                    ldm_x4t(aS + (uint32_t)(((st * AROWS + row) * ACOLS + col) * 2),
                            a[mi][0], a[mi][1], a[mi][2], a[mi][3]);
                }
            }
            uint32_t b[NF][2];
#pragma unroll
            for (int np = 0; np < NF / 2; np++) {
                int c0 = wn * WNT + np * 16;
                uint32_t q0, q1, q2, q3;
                if (OPB == 0) {
                    int row = k0 + tr + (tg & 1) * 8, col = c0 + (tg >> 1) * 8;
                    ldm_x4t(bS + (uint32_t)(((st * BROWS + row) * BCOLS + col) * 2), q0, q1, q2, q3);
                } else {
                    int row = c0 + tr + (tg >> 1) * 8, col = k0 + (tg & 1) * 8;
                    ldm_x4(bS + (uint32_t)(((st * BROWS + row) * BCOLS + col) * 2), q0, q1, q2, q3);
                }
                b[np * 2][0] = q0; b[np * 2][1] = q1;
                b[np * 2 + 1][0] = q2; b[np * 2 + 1][1] = q3;
            }
#pragma unroll
            for (int mi = 0; mi < 2; mi++)
#pragma unroll
                for (int ni = 0; ni < NF; ni++)
                    mma16816(acc[mi][ni], a[mi], b[ni]);
        }
        __syncthreads();
    }

    // ---------------- epilogue ----------------
    const float g = (EPI == 6 || EPI == 7) ? gam[0] : 0.f;
#pragma unroll
    for (int mi = 0; mi < 2; mi++) {
#pragma unroll
        for (int ni = 0; ni < NF; ni++) {
            int lr0 = wm * 32 + mi * 16 + (lane >> 2);
            int lc = wn * WNT + ni * 8 + (lane & 3) * 2;
            float* ac = acc[mi][ni];
#pragma unroll
            for (int hf = 0; hf < 2; hf++) {
                int r = lr0 + hf * 8;
                float v0 = ac[hf * 2 + 0], v1 = ac[hf * 2 + 1];
                long long idx = (long long)z * bsC + (long long)(m_base + r) * ldc + n_base + lc;
                if constexpr (EPI == 0) {
                    *reinterpret_cast<float2*>(Cf + idx) = make_float2(v0, v1);
                } else if constexpr (EPI == 6) {
                    float2 xv = *reinterpret_cast<const float2*>(Xin + idx);
                    *reinterpret_cast<__half2*>(Th + idx) =
                        __floats2half2_rn(3.f * xv.x + g * v0, 3.f * xv.y + g * v1);
                } else if constexpr (EPI == 7) {
                    __half2 tv = *reinterpret_cast<const __half2*>(Th + idx);
                    *reinterpret_cast<float2*>(Cf + idx) =
                        make_float2(__half2float(tv.x) + g * v0, __half2float(tv.y) + g * v1);
                }
            }
        }
    }
}

// ---------------- host launcher ----------------
template<int BM, int BN, int BK, int OPA, int OPB, int EPI, int BMODE>
static void launch_gemm(dim3 grid,
    const __half* A, const __half* B, float* Cf, __half* Th,
    const float* gam, const float* Xin,
    int K, int lda, int ldb, int ldc, long long bsA, long long bsB, long long bsC)
{
    constexpr int AR = OPA ? BK : BM, AC = (OPA ? BM : BK) + 8;
    constexpr int BR = OPB ? BN : BK, BC = (OPB ? BK : BN) + 8;
    constexpr int sz = 4 * (AR * AC + BR * BC);
    auto kfn = k_gemm<BM, BN, BK, OPA, OPB, EPI, BMODE>;
    cudaFuncSetAttribute(kfn, cudaFuncAttributeMaxDynamicSharedMemorySize, sz);
    kfn<<<grid, 256, sz>>>(A, B, Cf, Th, gam, Xin, K, lda, ldb, ldc, bsA, bsB, bsC);
}

extern "C" void kernel_launch(void* const* d_in, const int* in_sizes, int n_in,
                              void* d_out, int out_size)
{
    const float* x    = (const float*)d_in[0];
    const float* tq_w = (const float*)d_in[1];
    const float* tq_b = (const float*)d_in[2];
    const float* tk_w = (const float*)d_in[3];
    const float* tk_b = (const float*)d_in[4];
    const float* tv_w = (const float*)d_in[5];
    const float* tv_b = (const float*)d_in[6];
    const float* t_g  = (const float*)d_in[7];
    const float* fq_w = (const float*)d_in[8];
    const float* fq_b = (const float*)d_in[9];
    const float* fk_w = (const float*)d_in[10];
    const float* fk_b = (const float*)d_in[11];
    const float* fv_w = (const float*)d_in[12];
    const float* fv_b = (const float*)d_in[13];
    const float* f_g  = (const float*)d_in[14];
    float* out = (float*)d_out;

    __half *qt, *kt, *qf, *kf, *vt, *vf, *tmp, *attn;
    float* E;
    cudaGetSymbolAddress((void**)&qt, g_qt);
    cudaGetSymbolAddress((void**)&kt, g_kt);
    cudaGetSymbolAddress((void**)&qf, g_qf);
    cudaGetSymbolAddress((void**)&kf, g_kf);
    cudaGetSymbolAddress((void**)&vt, g_vt);
    cudaGetSymbolAddress((void**)&vf, g_vf);
    cudaGetSymbolAddress((void**)&tmp, g_tmp);
    cudaGetSymbolAddress((void**)&attn, g_attn);
    cudaGetSymbolAddress((void**)&E, g_E);

    k_pack_w<<<1, 256>>>(tq_w, tk_w, fq_w, fk_w, tq_b, tk_b, fq_b, fk_b,
                         tv_w, fv_w, tv_b, fv_b);

    // fused projection: all q/k/v for both passes, reading x fp32 directly
    k_proj<<<8192, 256>>>(x);

    // ---- time attention ----
    launch_gemm<128, 64, 64, 0, 1, 0, 0>(dim3(8, 4, 4),
        qt, kt, E, nullptr, nullptr, nullptr,
        4096, 4096, 4096, 512, 2097152LL, 2097152LL, 262144LL);
    k_softmax<<<2048, 256>>>();
    // tmp = 3x + gt * attn@v   (fp16), batch z=(n,c)
    launch_gemm<128, 128, 64, 0, 0, 6, 1>(dim3(4, 4, 256),
        attn, vt, nullptr, tmp, t_g, x,
        512, 512, 512, 512, 262144LL, 262144LL, 262144LL);

    // ---- freq attention ----
    launch_gemm<128, 64, 64, 1, 0, 0, 0>(dim3(8, 4, 4),
        qf, kf, E, nullptr, nullptr, nullptr,
        4096, 512, 512, 512, 2097152LL, 2097152LL, 262144LL);
    k_softmax<<<2048, 256>>>();
    // out = tmp + gf * v@attn^T   (fp32), per n
    launch_gemm<128, 128, 64, 0, 1, 7, 0>(dim3(4, 256, 4),
        vf, attn, out, tmp, f_g, nullptr,
        512, 512, 512, 512, 16777216LL, 262144LL, 16777216LL);
}

// round 8
// speedup vs baseline: 1.1349x; 1.0219x over previous
#include <cuda_runtime.h>
#include <cuda_fp16.h>
#include <cstdint>

// ---------------- static scratch ----------------
__device__ __half g_qt[8388608];       // time q  [n][h][c8][w]
__device__ __half g_kt[8388608];       // time k  [n][h][c8][w]
__device__ __half g_qf[8388608];       // freq q  [n][c8][h][w]
__device__ __half g_kf[8388608];       // freq k  [n][c8][h][w]
__device__ __half g_vt[67108864];      // time v  [n][c][g][w]   134 MB
__device__ __half g_vf[67108864];      // freq v  [n][c][h][w]   134 MB
__device__ __half g_tmp[67108864];     // time-pass partial (3x+gt*acc) fp16
__device__ float  g_E[4194304];        // energy partials fp32 [4][n][512][512]  16 MB
__device__ __half g_attn[1048576];     // attn fp16
__device__ __half g_wpack[10240];      // [160][64]: tq,tk,fq,fk,tv,fv
__device__ float  g_bpack[160];

// ---------------- helpers ----------------
__device__ __forceinline__ uint32_t smem_u32(const void* p) {
    return (uint32_t)__cvta_generic_to_shared(p);
}
__device__ __forceinline__ void cp16(uint32_t dst, const void* src) {
    asm volatile("cp.async.cg.shared.global [%0], [%1], 16;" :: "r"(dst), "l"(src));
}
__device__ __forceinline__ void cp_commit() {
    asm volatile("cp.async.commit_group;");
}
__device__ __forceinline__ void ldm_x4(uint32_t addr, uint32_t& r0, uint32_t& r1, uint32_t& r2, uint32_t& r3) {
    asm volatile("ldmatrix.sync.aligned.m8n8.x4.shared.b16 {%0,%1,%2,%3}, [%4];"
                 : "=r"(r0), "=r"(r1), "=r"(r2), "=r"(r3) : "r"(addr));
}
__device__ __forceinline__ void ldm_x4t(uint32_t addr, uint32_t& r0, uint32_t& r1, uint32_t& r2, uint32_t& r3) {
    asm volatile("ldmatrix.sync.aligned.m8n8.x4.trans.shared.b16 {%0,%1,%2,%3}, [%4];"
                 : "=r"(r0), "=r"(r1), "=r"(r2), "=r"(r3) : "r"(addr));
}
__device__ __forceinline__ void mma16816(float* c, const uint32_t* a, const uint32_t* b) {
    asm volatile("mma.sync.aligned.m16n8k16.row.col.f32.f16.f16.f32 "
                 "{%0,%1,%2,%3},{%4,%5,%6,%7},{%8,%9},{%0,%1,%2,%3};"
                 : "+f"(c[0]), "+f"(c[1]), "+f"(c[2]), "+f"(c[3])
                 : "r"(a[0]), "r"(a[1]), "r"(a[2]), "r"(a[3]), "r"(b[0]), "r"(b[1]));
}

// ---------------- weight packing ----------------
__global__ void k_pack_w(
    const float* __restrict__ tqw, const float* __restrict__ tkw,
    const float* __restrict__ fqw, const float* __restrict__ fkw,
    const float* __restrict__ tqb, const float* __restrict__ tkb,
    const float* __restrict__ fqb, const float* __restrict__ fkb,
    const float* __restrict__ tvw, const float* __restrict__ fvw,
    const float* __restrict__ tvb, const float* __restrict__ fvb)
{
    int t = threadIdx.x;
    for (int i = t; i < 512; i += 256) {
        g_wpack[i]        = __float2half(tqw[i]);
        g_wpack[512 + i]  = __float2half(tkw[i]);
        g_wpack[1024 + i] = __float2half(fqw[i]);
        g_wpack[1536 + i] = __float2half(fkw[i]);
    }
    for (int i = t; i < 4096; i += 256) {
        g_wpack[2048 + i] = __float2half(tvw[i]);
        g_wpack[6144 + i] = __float2half(fvw[i]);
    }
    if (t < 8) {
        g_bpack[t] = tqb[t]; g_bpack[8 + t] = tkb[t];
        g_bpack[16 + t] = fqb[t]; g_bpack[24 + t] = fkb[t];
    }
    if (t < 64) { g_bpack[32 + t] = tvb[t]; g_bpack[96 + t] = fvb[t]; }
}

// ---------------- fused projection (proven R5) ----------------
__global__ __launch_bounds__(256) void k_proj(const float* __restrict__ x)
{
    __shared__ __align__(16) __half Ws[160][72];
    __shared__ __align__(16) __half Xs[64][136];
    __shared__ float Bb[160];

    const int tid = threadIdx.x;
    const int warp = tid >> 5, lane = tid & 31;
    const int wm = warp >> 2, wn = warp & 3;
    const int tr = lane & 7, tg = lane >> 3;

    const int nb = blockIdx.x >> 11;
    const int chunk = blockIdx.x & 2047;
    const long long pix0 = (long long)chunk * 128;
    const int h = (int)(pix0 >> 9);
    const int w0 = (int)(pix0 & 511);

    uint32_t wS = smem_u32(&Ws[0][0]);
    for (int c = tid; c < 1280; c += 256) {
        int r = c >> 3, s = (c & 7) * 8;
        cp16(wS + (uint32_t)((r * 72 + s) * 2), g_wpack + r * 64 + s);
    }
    cp_commit();
    if (tid < 160) Bb[tid] = g_bpack[tid];

    const float4* x4 = reinterpret_cast<const float4*>(x) + (long long)nb * 4194304 + (pix0 >> 2);
    for (int i = tid; i < 2048; i += 256) {
        int c = i >> 5, f4 = i & 31;
        float4 f = x4[(long long)c * 65536 + f4];
        *reinterpret_cast<__half2*>(&Xs[c][f4 * 4])     = __floats2half2_rn(f.x, f.y);
        *reinterpret_cast<__half2*>(&Xs[c][f4 * 4 + 2]) = __floats2half2_rn(f.z, f.w);
    }
    asm volatile("cp.async.wait_group 0;" ::: "memory");
    __syncthreads();

    uint32_t xS = smem_u32(&Xs[0][0]);
    float acc[5][4][4];
#pragma unroll
    for (int mi = 0; mi < 5; mi++)
#pragma unroll
        for (int ni = 0; ni < 4; ni++)
#pragma unroll
            for (int j = 0; j < 4; j++) acc[mi][ni][j] = 0.f;

#pragma unroll
    for (int ks = 0; ks < 4; ks++) {
        const int k0 = ks * 16;
        uint32_t a[5][4];
#pragma unroll
        for (int mi = 0; mi < 5; mi++) {
            int row = wm * 80 + mi * 16 + tr + (tg & 1) * 8;
            int col = k0 + (tg >> 1) * 8;
            ldm_x4(wS + (uint32_t)((row * 72 + col) * 2), a[mi][0], a[mi][1], a[mi][2], a[mi][3]);
        }
        uint32_t b[4][2];
#pragma unroll
        for (int np = 0; np < 2; np++) {
            int row = k0 + tr + (tg & 1) * 8;
            int col = wn * 32 + np * 16 + (tg >> 1) * 8;
            uint32_t q0, q1, q2, q3;
            ldm_x4t(xS + (uint32_t)((row * 136 + col) * 2), q0, q1, q2, q3);
            b[np * 2][0] = q0; b[np * 2][1] = q1;
            b[np * 2 + 1][0] = q2; b[np * 2 + 1][1] = q3;
        }
#pragma unroll
        for (int mi = 0; mi < 5; mi++)
#pragma unroll
            for (int ni = 0; ni < 4; ni++)
                mma16816(acc[mi][ni], a[mi], b[ni]);
    }

#pragma unroll
    for (int mi = 0; mi < 5; mi++) {
#pragma unroll
        for (int ni = 0; ni < 4; ni++) {
            int lc = wn * 32 + ni * 8 + (lane & 3) * 2;
#pragma unroll
            for (int hf = 0; hf < 2; hf++) {
                int r = wm * 80 + mi * 16 + (lane >> 2) + hf * 8;
                float bv = Bb[r];
                __half2 hv = __floats2half2_rn(acc[mi][ni][hf * 2] + bv,
                                               acc[mi][ni][hf * 2 + 1] + bv);
                __half* dst;
                if (r < 32) {
                    int kind = r >> 3;
                    __half* base = kind == 0 ? g_qt : kind == 1 ? g_kt : kind == 2 ? g_qf : g_kf;
                    long long o = (long long)nb * 2097152;
                    if (kind < 2) dst = base + o + (long long)h * 4096 + (r & 7) * 512 + w0 + lc;
                    else          dst = base + o + (long long)(r & 7) * 262144 + pix0 + lc;
                } else {
                    int r2 = r - 32;
                    __half* base = (r2 < 64) ? g_vt : g_vf;
                    int cc = (r2 < 64) ? r2 : r2 - 64;
                    dst = base + (long long)nb * 16777216 + (long long)cc * 262144 + pix0 + lc;
                }
                *reinterpret_cast<__half2*>(dst) = hv;
            }
        }
    }
}

// ---------------- softmax over rows of 512, fused split-K reduction ----------------
__global__ __launch_bounds__(256) void k_softmax() {
    int r = blockIdx.x, t = threadIdx.x;
    const float* e = g_E + (long long)r * 512;
    float v0 = e[t]           + e[t + 1048576]       + e[t + 2097152]       + e[t + 3145728];
    float v1 = e[t + 256]     + e[t + 256 + 1048576] + e[t + 256 + 2097152] + e[t + 256 + 3145728];

    __shared__ float red[8];
    float m = fmaxf(v0, v1);
#pragma unroll
    for (int o = 16; o; o >>= 1) m = fmaxf(m, __shfl_xor_sync(0xffffffffu, m, o));
    if ((t & 31) == 0) red[t >> 5] = m;
    __syncthreads();
    float M = red[0];
#pragma unroll
    for (int i = 1; i < 8; i++) M = fmaxf(M, red[i]);
    __syncthreads();

    float e0 = __expf(v0 - M), e1 = __expf(v1 - M);
    float s = e0 + e1;
#pragma unroll
    for (int o = 16; o; o >>= 1) s += __shfl_xor_sync(0xffffffffu, s, o);
    if ((t & 31) == 0) red[t >> 5] = s;
    __syncthreads();
    float S = 0.f;
#pragma unroll
    for (int i = 0; i < 8; i++) S += red[i];
    float inv = 1.f / S;

    __half* a = g_attn + (long long)r * 512;
    a[t] = __float2half(e0 * inv);
    a[t + 256] = __float2half(e1 * inv);
}

// ---------------- split-K energy GEMM (mma.sync, 2-stage) ----------------
// M=N=512 per n, K=4096 split into 4 chunks of 1024.
// OPA: 0 -> A[m][k], 1 -> A[k][m].  OPB: 0 -> B[k][n], 1 -> B[n][k].
// blockIdx.z: low 2 bits = n, high bits = kc (K-chunk). Partial written to g_E + kc*1048576.
template<int BM, int BN, int BK, int OPA, int OPB>
__global__ __launch_bounds__(256) void k_energy(
    const __half* __restrict__ Ag, const __half* __restrict__ Bg,
    int lda, int ldb)
{
    constexpr int WM_ = BM / 32;
    constexpr int WNT = BN / (8 / WM_);
    constexpr int NF = WNT / 8;
    constexpr int KS = BK / 16;
    constexpr int KT = 1024 / BK;
    constexpr int AROWS = OPA ? BK : BM;
    constexpr int ACOLS = (OPA ? BM : BK) + 8;
    constexpr int BROWS = OPB ? BN : BK;
    constexpr int BCOLS = (OPB ? BK : BN) + 8;

    extern __shared__ __align__(16) char dsm[];
    uint32_t aS = smem_u32(dsm);
    uint32_t bS = aS + (uint32_t)(2 * AROWS * ACOLS * 2);

    const int tid = threadIdx.x;
    const int warp = tid >> 5, lane = tid & 31;
    const int wm = warp % WM_, wn = warp / WM_;
    const int tr = lane & 7, tg = lane >> 3;

    const int n = blockIdx.z & 3;
    const int kc = blockIdx.z >> 2;
    const int n_base = blockIdx.x * BN;
    const int m_base = blockIdx.y * BM;

    const __half* Ab = Ag + (long long)n * 2097152
        + (OPA ? ((long long)m_base + (long long)kc * 1024 * lda)
               : ((long long)m_base * lda + kc * 1024));
    const __half* Bb = Bg + (long long)n * 2097152
        + (OPB ? ((long long)n_base * ldb + kc * 1024)
               : ((long long)n_base + (long long)kc * 1024 * ldb));

    auto load_tile = [&](int st, int kt) {
        {
            constexpr int CH = (OPA ? BM : BK) / 8;
            constexpr int TOT = AROWS * CH;
#pragma unroll
            for (int c0 = 0; c0 < TOT; c0 += 256) {
                int c = c0 + tid;
                int r = c / CH, s = (c % CH) * 8;
                const __half* src = OPA ? (Ab + (long long)(kt * BK + r) * lda + s)
                                        : (Ab + (long long)r * lda + kt * BK + s);
                cp16(aS + (uint32_t)(((st * AROWS + r) * ACOLS + s) * 2), src);
            }
        }
        {
            constexpr int CH = (OPB ? BK : BN) / 8;
            constexpr int TOT = BROWS * CH;
#pragma unroll
            for (int c0 = 0; c0 < TOT; c0 += 256) {
                int c = c0 + tid;
                int r = c / CH, s = (c % CH) * 8;
                const __half* src = OPB ? (Bb + (long long)r * ldb + kt * BK + s)
                                        : (Bb + (long long)(kt * BK + r) * ldb + s);
                cp16(bS + (uint32_t)(((st * BROWS + r) * BCOLS + s) * 2), src);
            }
        }
        cp_commit();
    };

    float acc[2][NF][4];
#pragma unroll
    for (int mi = 0; mi < 2; mi++)
#pragma unroll
        for (int ni = 0; ni < NF; ni++)
#pragma unroll
            for (int j = 0; j < 4; j++) acc[mi][ni][j] = 0.f;

    load_tile(0, 0);

    for (int kt = 0; kt < KT; kt++) {
        if (kt + 1 < KT) {
            load_tile((kt + 1) & 1, kt + 1);
            asm volatile("cp.async.wait_group 1;" ::: "memory");
        } else {
            asm volatile("cp.async.wait_group 0;" ::: "memory");
        }
        __syncthreads();

        const int st = kt & 1;
#pragma unroll
        for (int ks = 0; ks < KS; ks++) {
            const int k0 = ks * 16;
            uint32_t a[2][4];
#pragma unroll
            for (int mi = 0; mi < 2; mi++) {
                int r0 = wm * 32 + mi * 16;
                if (OPA == 0) {
                    int row = r0 + tr + (tg & 1) * 8, col = k0 + (tg >> 1) * 8;
                    ldm_x4(aS + (uint32_t)(((st * AROWS + row) * ACOLS + col) * 2),
                           a[mi][0], a[mi][1], a[mi][2], a[mi][3]);
                } else {
                    int row = k0 + tr + (tg >> 1) * 8, col = r0 + (tg & 1) * 8;
                    ldm_x4t(aS + (uint32_t)(((st * AROWS + row) * ACOLS + col) * 2),
                            a[mi][0], a[mi][1], a[mi][2], a[mi][3]);
                }
            }
            uint32_t b[NF][2];
#pragma unroll
            for (int np = 0; np < NF / 2; np++) {
                int c0 = wn * WNT + np * 16;
                uint32_t q0, q1, q2, q3;
                if (OPB == 0) {
                    int row = k0 + tr + (tg & 1) * 8, col = c0 + (tg >> 1) * 8;
                    ldm_x4t(bS + (uint32_t)(((st * BROWS + row) * BCOLS + col) * 2), q0, q1, q2, q3);
                } else {
                    int row = c0 + tr + (tg >> 1) * 8, col = k0 + (tg & 1) * 8;
                    ldm_x4(bS + (uint32_t)(((st * BROWS + row) * BCOLS + col) * 2), q0, q1, q2, q3);
                }
                b[np * 2][0] = q0; b[np * 2][1] = q1;
                b[np * 2 + 1][0] = q2; b[np * 2 + 1][1] = q3;
            }
#pragma unroll
            for (int mi = 0; mi < 2; mi++)
#pragma unroll
                for (int ni = 0; ni < NF; ni++)
                    mma16816(acc[mi][ni], a[mi], b[ni]);
        }
        __syncthreads();
    }

    float* Cf = g_E + (long long)kc * 1048576 + (long long)n * 262144;
#pragma unroll
    for (int mi = 0; mi < 2; mi++) {
#pragma unroll
        for (int ni = 0; ni < NF; ni++) {
            int lr0 = wm * 32 + mi * 16 + (lane >> 2);
            int lc = wn * WNT + ni * 8 + (lane & 3) * 2;
            float* ac = acc[mi][ni];
#pragma unroll
            for (int hf = 0; hf < 2; hf++) {
                int r = lr0 + hf * 8;
                long long idx = (long long)(m_base + r) * 512 + n_base + lc;
                *reinterpret_cast<float2*>(Cf + idx) = make_float2(ac[hf * 2], ac[hf * 2 + 1]);
            }
        }
    }
}

// ---------------- out GEMM (mma.sync, 2-stage — proven R2/R5 mainloop) ----------------
// OPA: 0 -> A[m][k], 1 -> A[k][m].   OPB: 0 -> B[k][n], 1 -> B[n][k].
// EPI: 6 tmp_half = 3*Xin + g*acc | 7 Cf = tmp_half + g*acc
// BMODE: 0 -> offA=z*bsA | 1 -> offA=(z>>6)*bsA
template<int BM, int BN, int BK, int OPA, int OPB, int EPI, int BMODE>
__global__ __launch_bounds__(256) void k_gemm(
    const __half* __restrict__ Ag, const __half* __restrict__ Bg,
    float* __restrict__ Cf, __half* __restrict__ Th,
    const float* __restrict__ gam, const float* __restrict__ Xin,
    int K, int lda, int ldb, int ldc,
    long long bsA, long long bsB, long long bsC)
{
    constexpr int WM_ = BM / 32;
    constexpr int WNT = BN / (8 / WM_);
    constexpr int NF = WNT / 8;
    constexpr int KS = BK / 16;
    constexpr int AROWS = OPA ? BK : BM;
    constexpr int ACOLS = (OPA ? BM : BK) + 8;
    constexpr int BROWS = OPB ? BN : BK;
    constexpr int BCOLS = (OPB ? BK : BN) + 8;

    extern __shared__ __align__(16) char dsm[];
    uint32_t aS = smem_u32(dsm);
    uint32_t bS = aS + (uint32_t)(2 * AROWS * ACOLS * 2);

    const int tid = threadIdx.x;
    const int warp = tid >> 5, lane = tid & 31;
    const int wm = warp % WM_, wn = warp / WM_;
    const int tr = lane & 7, tg = lane >> 3;

    const int z = blockIdx.z;
    const int n_base = blockIdx.x * BN;
    const int m_base = blockIdx.y * BM;

    long long offA = (BMODE == 1 ? (long long)(z >> 6) : (long long)z) * bsA;
    const __half* Ab = Ag + offA + (OPA ? (long long)m_base : (long long)m_base * lda);
    const __half* Bb = Bg + (long long)z * bsB + (OPB ? (long long)n_base * ldb : (long long)n_base);

    const int KT = K / BK;

    auto load_tile = [&](int st, int kt) {
        {
            constexpr int CH = (OPA ? BM : BK) / 8;
            constexpr int TOT = AROWS * CH;
#pragma unroll
            for (int c0 = 0; c0 < TOT; c0 += 256) {
                int c = c0 + tid;
                int r = c / CH, s = (c % CH) * 8;
                const __half* src = OPA ? (Ab + (long long)(kt * BK + r) * lda + s)
                                        : (Ab + (long long)r * lda + kt * BK + s);
                cp16(aS + (uint32_t)(((st * AROWS + r) * ACOLS + s) * 2), src);
            }
        }
        {
            constexpr int CH = (OPB ? BK : BN) / 8;
            constexpr int TOT = BROWS * CH;
#pragma unroll
            for (int c0 = 0; c0 < TOT; c0 += 256) {
                int c = c0 + tid;
                int r = c / CH, s = (c % CH) * 8;
                const __half* src = OPB ? (Bb + (long long)r * ldb + kt * BK + s)
                                        : (Bb + (long long)(kt * BK + r) * ldb + s);
                cp16(bS + (uint32_t)(((st * BROWS + r) * BCOLS + s) * 2), src);
            }
        }
        cp_commit();
    };

    float acc[2][NF][4];
#pragma unroll
    for (int mi = 0; mi < 2; mi++)
#pragma unroll
        for (int ni = 0; ni < NF; ni++)
#pragma unroll
            for (int j = 0; j < 4; j++) acc[mi][ni][j] = 0.f;

    load_tile(0, 0);

    for (int kt = 0; kt < KT; kt++) {
        if (kt + 1 < KT) {
            load_tile((kt + 1) & 1, kt + 1);
            asm volatile("cp.async.wait_group 1;" ::: "memory");
        } else {
            asm volatile("cp.async.wait_group 0;" ::: "memory");
        }
        __syncthreads();

        const int st = kt & 1;
#pragma unroll
        for (int ks = 0; ks < KS; ks++) {
            const int k0 = ks * 16;
            uint32_t a[2][4];
#pragma unroll
            for (int mi = 0; mi < 2; mi++) {
                int r0 = wm * 32 + mi * 16;
                if (OPA == 0) {
                    int row = r0 + tr + (tg & 1) * 8, col = k0 + (tg >> 1) * 8;
                    ldm_x4(aS + (uint32_t)(((st * AROWS + row) * ACOLS + col) * 2),
                           a[mi][0], a[mi][1], a[mi][2], a[mi][3]);
                } else {
                    int row = k0 + tr + (tg >> 1) * 8, col = r0 + (tg & 1) * 8;
                    ldm_x4t(aS + (uint32_t)(((st * AROWS + row) * ACOLS + col) * 2),
                            a[mi][0], a[mi][1], a[mi][2], a[mi][3]);
                }
            }
            uint32_t b[NF][2];
#pragma unroll
            for (int np = 0; np < NF / 2; np++) {
                int c0 = wn * WNT + np * 16;
                uint32_t q0, q1, q2, q3;
                if (OPB == 0) {
                    int row = k0 + tr + (tg & 1) * 8, col = c0 + (tg >> 1) * 8;
                    ldm_x4t(bS + (uint32_t)(((st * BROWS + row) * BCOLS + col) * 2), q0, q1, q2, q3);
                } else {
                    int row = c0 + tr + (tg >> 1) * 8, col = k0 + (tg & 1) * 8;
                    ldm_x4(bS + (uint32_t)(((st * BROWS + row) * BCOLS + col) * 2), q0, q1, q2, q3);
                }
                b[np * 2][0] = q0; b[np * 2][1] = q1;
                b[np * 2 + 1][0] = q2; b[np * 2 + 1][1] = q3;
            }
#pragma unroll
            for (int mi = 0; mi < 2; mi++)
#pragma unroll
                for (int ni = 0; ni < NF; ni++)
                    mma16816(acc[mi][ni], a[mi], b[ni]);
        }
        __syncthreads();
    }

    const float g = gam[0];
#pragma unroll
    for (int mi = 0; mi < 2; mi++) {
#pragma unroll
        for (int ni = 0; ni < NF; ni++) {
            int lr0 = wm * 32 + mi * 16 + (lane >> 2);
            int lc = wn * WNT + ni * 8 + (lane & 3) * 2;
            float* ac = acc[mi][ni];
#pragma unroll
            for (int hf = 0; hf < 2; hf++) {
                int r = lr0 + hf * 8;
                float v0 = ac[hf * 2 + 0], v1 = ac[hf * 2 + 1];
                long long idx = (long long)z * bsC + (long long)(m_base + r) * ldc + n_base + lc;
                if constexpr (EPI == 6) {
                    float2 xv = *reinterpret_cast<const float2*>(Xin + idx);
                    *reinterpret_cast<__half2*>(Th + idx) =
                        __floats2half2_rn(3.f * xv.x + g * v0, 3.f * xv.y + g * v1);
                } else {
                    __half2 tv = *reinterpret_cast<const __half2*>(Th + idx);
                    *reinterpret_cast<float2*>(Cf + idx) =
                        make_float2(__half2float(tv.x) + g * v0, __half2float(tv.y) + g * v1);
                }
            }
        }
    }
}

// ---------------- host launchers ----------------
template<int BM, int BN, int BK, int OPA, int OPB>
static void launch_energy(const __half* A, const __half* B, int lda, int ldb)
{
    constexpr int AR = OPA ? BK : BM, AC = (OPA ? BM : BK) + 8;
    constexpr int BR = OPB ? BN : BK, BC = (OPB ? BK : BN) + 8;
    constexpr int sz = 4 * (AR * AC + BR * BC);
    auto kfn = k_energy<BM, BN, BK, OPA, OPB>;
    cudaFuncSetAttribute(kfn, cudaFuncAttributeMaxDynamicSharedMemorySize, sz);
    kfn<<<dim3(512 / BN, 512 / BM, 16), 256, sz>>>(A, B, lda, ldb);
}

template<int BM, int BN, int BK, int OPA, int OPB, int EPI, int BMODE>
static void launch_gemm(dim3 grid,
    const __half* A, const __half* B, float* Cf, __half* Th,
    const float* gam, const float* Xin,
    int K, int lda, int ldb, int ldc, long long bsA, long long bsB, long long bsC)
{
    constexpr int AR = OPA ? BK : BM, AC = (OPA ? BM : BK) + 8;
    constexpr int BR = OPB ? BN : BK, BC = (OPB ? BK : BN) + 8;
    constexpr int sz = 4 * (AR * AC + BR * BC);
    auto kfn = k_gemm<BM, BN, BK, OPA, OPB, EPI, BMODE>;
    cudaFuncSetAttribute(kfn, cudaFuncAttributeMaxDynamicSharedMemorySize, sz);
    kfn<<<grid, 256, sz>>>(A, B, Cf, Th, gam, Xin, K, lda, ldb, ldc, bsA, bsB, bsC);
}

extern "C" void kernel_launch(void* const* d_in, const int* in_sizes, int n_in,
                              void* d_out, int out_size)
{
    const float* x    = (const float*)d_in[0];
    const float* tq_w = (const float*)d_in[1];
    const float* tq_b = (const float*)d_in[2];
    const float* tk_w = (const float*)d_in[3];
    const float* tk_b = (const float*)d_in[4];
    const float* tv_w = (const float*)d_in[5];
    const float* tv_b = (const float*)d_in[6];
    const float* t_g  = (const float*)d_in[7];
    const float* fq_w = (const float*)d_in[8];
    const float* fq_b = (const float*)d_in[9];
    const float* fk_w = (const float*)d_in[10];
    const float* fk_b = (const float*)d_in[11];
    const float* fv_w = (const float*)d_in[12];
    const float* fv_b = (const float*)d_in[13];
    const float* f_g  = (const float*)d_in[14];
    float* out = (float*)d_out;

    __half *qt, *kt, *qf, *kf, *vt, *vf, *tmp, *attn;
    cudaGetSymbolAddress((void**)&qt, g_qt);
    cudaGetSymbolAddress((void**)&kt, g_kt);
    cudaGetSymbolAddress((void**)&qf, g_qf);
    cudaGetSymbolAddress((void**)&kf, g_kf);
    cudaGetSymbolAddress((void**)&vt, g_vt);
    cudaGetSymbolAddress((void**)&vf, g_vf);
    cudaGetSymbolAddress((void**)&tmp, g_tmp);
    cudaGetSymbolAddress((void**)&attn, g_attn);

    k_pack_w<<<1, 256>>>(tq_w, tk_w, fq_w, fk_w, tq_b, tk_b, fq_b, fk_b,
                         tv_w, fv_w, tv_b, fv_b);
    k_proj<<<8192, 256>>>(x);

    // ---- time attention ----
    // energy NT split-K: A=qt[h][g*w] lda=4096, B=kt[g*w] per-row (OPB=1) ldb=4096
    launch_energy<128, 64, 64, 0, 1>(qt, kt, 4096, 4096);
    k_softmax<<<2048, 256>>>();
    // tmp = 3x + gt * attn@v   (fp16), batch z=(n,c)
    launch_gemm<128, 128, 64, 0, 0, 6, 1>(dim3(4, 4, 256),
        attn, vt, nullptr, tmp, t_g, x,
        512, 512, 512, 512, 262144LL, 262144LL, 262144LL);

    // ---- freq attention ----
    // energy TN split-K: A=qf[k][m] lda=512 (OPA=1), B=kf[k][n] ldb=512 (OPB=0)
    launch_energy<128, 64, 64, 1, 0>(qf, kf, 512, 512);
    k_softmax<<<2048, 256>>>();
    // out = tmp + gf * v@attn^T   (fp32), per n
    launch_gemm<128, 128, 64, 0, 1, 7, 0>(dim3(4, 256, 4),
        vf, attn, out, tmp, f_g, nullptr,
        512, 512, 512, 512, 16777216LL, 262144LL, 16777216LL);
}

// round 9
// speedup vs baseline: 1.1438x; 1.0078x over previous
#include <cuda_runtime.h>
#include <cuda_fp16.h>
#include <cstdint>

// ---------------- static scratch ----------------
__device__ __half g_qt[8388608];       // time q  [n][h][c8][w]
__device__ __half g_kt[8388608];       // time k  [n][h][c8][w]
__device__ __half g_qf[8388608];       // freq q  [n][c8][h][w]
__device__ __half g_kf[8388608];       // freq k  [n][c8][h][w]
__device__ __half g_vt[67108864];      // time v  [n][c][g][w]   134 MB
__device__ __half g_vf[67108864];      // freq v  [n][c][h][w]   134 MB
__device__ __half g_tmp[67108864];     // time-pass partial (3x+gt*acc) fp16
__device__ float  g_E[4194304];        // time energy partials [4][n][512][512] 16 MB
__device__ float  g_Ef[4194304];       // freq energy partials [4][n][512][512] 16 MB
__device__ __half g_attn[2097152];     // attn fp16: [0]=time, [1048576]=freq
__device__ __half g_wpack[10240];      // [160][64]: tq,tk,fq,fk,tv,fv
__device__ float  g_bpack[160];

// ---------------- helpers ----------------
__device__ __forceinline__ uint32_t smem_u32(const void* p) {
    return (uint32_t)__cvta_generic_to_shared(p);
}
__device__ __forceinline__ void cp16(uint32_t dst, const void* src) {
    asm volatile("cp.async.cg.shared.global [%0], [%1], 16;" :: "r"(dst), "l"(src));
}
__device__ __forceinline__ void cp_commit() {
    asm volatile("cp.async.commit_group;");
}
__device__ __forceinline__ void ldm_x4(uint32_t addr, uint32_t& r0, uint32_t& r1, uint32_t& r2, uint32_t& r3) {
    asm volatile("ldmatrix.sync.aligned.m8n8.x4.shared.b16 {%0,%1,%2,%3}, [%4];"
                 : "=r"(r0), "=r"(r1), "=r"(r2), "=r"(r3) : "r"(addr));
}
__device__ __forceinline__ void ldm_x4t(uint32_t addr, uint32_t& r0, uint32_t& r1, uint32_t& r2, uint32_t& r3) {
    asm volatile("ldmatrix.sync.aligned.m8n8.x4.trans.shared.b16 {%0,%1,%2,%3}, [%4];"
                 : "=r"(r0), "=r"(r1), "=r"(r2), "=r"(r3) : "r"(addr));
}
__device__ __forceinline__ void mma16816(float* c, const uint32_t* a, const uint32_t* b) {
    asm volatile("mma.sync.aligned.m16n8k16.row.col.f32.f16.f16.f32 "
                 "{%0,%1,%2,%3},{%4,%5,%6,%7},{%8,%9},{%0,%1,%2,%3};"
                 : "+f"(c[0]), "+f"(c[1]), "+f"(c[2]), "+f"(c[3])
                 : "r"(a[0]), "r"(a[1]), "r"(a[2]), "r"(a[3]), "r"(b[0]), "r"(b[1]));
}

// ---------------- weight packing ----------------
__global__ void k_pack_w(
    const float* __restrict__ tqw, const float* __restrict__ tkw,
    const float* __restrict__ fqw, const float* __restrict__ fkw,
    const float* __restrict__ tqb, const float* __restrict__ tkb,
    const float* __restrict__ fqb, const float* __restrict__ fkb,
    const float* __restrict__ tvw, const float* __restrict__ fvw,
    const float* __restrict__ tvb, const float* __restrict__ fvb)
{
    int t = threadIdx.x;
    for (int i = t; i < 512; i += 256) {
        g_wpack[i]        = __float2half(tqw[i]);
        g_wpack[512 + i]  = __float2half(tkw[i]);
        g_wpack[1024 + i] = __float2half(fqw[i]);
        g_wpack[1536 + i] = __float2half(fkw[i]);
    }
    for (int i = t; i < 4096; i += 256) {
        g_wpack[2048 + i] = __float2half(tvw[i]);
        g_wpack[6144 + i] = __float2half(fvw[i]);
    }
    if (t < 8) {
        g_bpack[t] = tqb[t]; g_bpack[8 + t] = tkb[t];
        g_bpack[16 + t] = fqb[t]; g_bpack[24 + t] = fkb[t];
    }
    if (t < 64) { g_bpack[32 + t] = tvb[t]; g_bpack[96 + t] = fvb[t]; }
}

// ---------------- fused projection (proven R5) ----------------
__global__ __launch_bounds__(256) void k_proj(const float* __restrict__ x)
{
    __shared__ __align__(16) __half Ws[160][72];
    __shared__ __align__(16) __half Xs[64][136];
    __shared__ float Bb[160];

    const int tid = threadIdx.x;
    const int warp = tid >> 5, lane = tid & 31;
    const int wm = warp >> 2, wn = warp & 3;
    const int tr = lane & 7, tg = lane >> 3;

    const int nb = blockIdx.x >> 11;
    const int chunk = blockIdx.x & 2047;
    const long long pix0 = (long long)chunk * 128;
    const int h = (int)(pix0 >> 9);
    const int w0 = (int)(pix0 & 511);

    uint32_t wS = smem_u32(&Ws[0][0]);
    for (int c = tid; c < 1280; c += 256) {
        int r = c >> 3, s = (c & 7) * 8;
        cp16(wS + (uint32_t)((r * 72 + s) * 2), g_wpack + r * 64 + s);
    }
    cp_commit();
    if (tid < 160) Bb[tid] = g_bpack[tid];

    const float4* x4 = reinterpret_cast<const float4*>(x) + (long long)nb * 4194304 + (pix0 >> 2);
    for (int i = tid; i < 2048; i += 256) {
        int c = i >> 5, f4 = i & 31;
        float4 f = x4[(long long)c * 65536 + f4];
        *reinterpret_cast<__half2*>(&Xs[c][f4 * 4])     = __floats2half2_rn(f.x, f.y);
        *reinterpret_cast<__half2*>(&Xs[c][f4 * 4 + 2]) = __floats2half2_rn(f.z, f.w);
    }
    asm volatile("cp.async.wait_group 0;" ::: "memory");
    __syncthreads();

    uint32_t xS = smem_u32(&Xs[0][0]);
    float acc[5][4][4];
#pragma unroll
    for (int mi = 0; mi < 5; mi++)
#pragma unroll
        for (int ni = 0; ni < 4; ni++)
#pragma unroll
            for (int j = 0; j < 4; j++) acc[mi][ni][j] = 0.f;

#pragma unroll
    for (int ks = 0; ks < 4; ks++) {
        const int k0 = ks * 16;
        uint32_t a[5][4];
#pragma unroll
        for (int mi = 0; mi < 5; mi++) {
            int row = wm * 80 + mi * 16 + tr + (tg & 1) * 8;
            int col = k0 + (tg >> 1) * 8;
            ldm_x4(wS + (uint32_t)((row * 72 + col) * 2), a[mi][0], a[mi][1], a[mi][2], a[mi][3]);
        }
        uint32_t b[4][2];
#pragma unroll
        for (int np = 0; np < 2; np++) {
            int row = k0 + tr + (tg & 1) * 8;
            int col = wn * 32 + np * 16 + (tg >> 1) * 8;
            uint32_t q0, q1, q2, q3;
            ldm_x4t(xS + (uint32_t)((row * 136 + col) * 2), q0, q1, q2, q3);
            b[np * 2][0] = q0; b[np * 2][1] = q1;
            b[np * 2 + 1][0] = q2; b[np * 2 + 1][1] = q3;
        }
#pragma unroll
        for (int mi = 0; mi < 5; mi++)
#pragma unroll
            for (int ni = 0; ni < 4; ni++)
                mma16816(acc[mi][ni], a[mi], b[ni]);
    }

#pragma unroll
    for (int mi = 0; mi < 5; mi++) {
#pragma unroll
        for (int ni = 0; ni < 4; ni++) {
            int lc = wn * 32 + ni * 8 + (lane & 3) * 2;
#pragma unroll
            for (int hf = 0; hf < 2; hf++) {
                int r = wm * 80 + mi * 16 + (lane >> 2) + hf * 8;
                float bv = Bb[r];
                __half2 hv = __floats2half2_rn(acc[mi][ni][hf * 2] + bv,
                                               acc[mi][ni][hf * 2 + 1] + bv);
                __half* dst;
                if (r < 32) {
                    int kind = r >> 3;
                    __half* base = kind == 0 ? g_qt : kind == 1 ? g_kt : kind == 2 ? g_qf : g_kf;
                    long long o = (long long)nb * 2097152;
                    if (kind < 2) dst = base + o + (long long)h * 4096 + (r & 7) * 512 + w0 + lc;
                    else          dst = base + o + (long long)(r & 7) * 262144 + pix0 + lc;
                } else {
                    int r2 = r - 32;
                    __half* base = (r2 < 64) ? g_vt : g_vf;
                    int cc = (r2 < 64) ? r2 : r2 - 64;
                    dst = base + (long long)nb * 16777216 + (long long)cc * 262144 + pix0 + lc;
                }
                *reinterpret_cast<__half2*>(dst) = hv;
            }
        }
    }
}

// ---------------- combined softmax (4096 rows: [0,2048)=time, [2048,4096)=freq) ----------------
__global__ __launch_bounds__(256) void k_softmax_both() {
    int r = blockIdx.x, t = threadIdx.x;
    int rr = r & 2047;
    const float* e = (r < 2048 ? g_E : g_Ef) + (long long)rr * 512;
    float v0 = e[t]       + e[t + 1048576]       + e[t + 2097152]       + e[t + 3145728];
    float v1 = e[t + 256] + e[t + 256 + 1048576] + e[t + 256 + 2097152] + e[t + 256 + 3145728];

    __shared__ float red[8];
    float m = fmaxf(v0, v1);
#pragma unroll
    for (int o = 16; o; o >>= 1) m = fmaxf(m, __shfl_xor_sync(0xffffffffu, m, o));
    if ((t & 31) == 0) red[t >> 5] = m;
    __syncthreads();
    float M = red[0];
#pragma unroll
    for (int i = 1; i < 8; i++) M = fmaxf(M, red[i]);
    __syncthreads();

    float e0 = __expf(v0 - M), e1 = __expf(v1 - M);
    float s = e0 + e1;
#pragma unroll
    for (int o = 16; o; o >>= 1) s += __shfl_xor_sync(0xffffffffu, s, o);
    if ((t & 31) == 0) red[t >> 5] = s;
    __syncthreads();
    float S = 0.f;
#pragma unroll
    for (int i = 0; i < 8; i++) S += red[i];
    float inv = 1.f / S;

    __half* a = g_attn + (r < 2048 ? 0 : 1048576) + (long long)rr * 512;
    a[t] = __float2half(e0 * inv);
    a[t + 256] = __float2half(e1 * inv);
}

// ---------------- energy GEMM body (device, templated) ----------------
// Computes C[m_base:+BM][n_base:+BN] partial over K=1024, writes fp32 to Cf (ldc=512).
template<int BM, int BN, int BK, int OPA, int OPB>
__device__ __forceinline__ void energy_body(
    const __half* __restrict__ Ab, const __half* __restrict__ Bb,
    float* __restrict__ Cf, int lda, int ldb, int m_base, int n_base)
{
    constexpr int WM_ = BM / 32;
    constexpr int WNT = BN / (8 / WM_);
    constexpr int NF = WNT / 8;
    constexpr int KS = BK / 16;
    constexpr int KT = 1024 / BK;
    constexpr int AROWS = OPA ? BK : BM;
    constexpr int ACOLS = (OPA ? BM : BK) + 8;
    constexpr int BROWS = OPB ? BN : BK;
    constexpr int BCOLS = (OPB ? BK : BN) + 8;

    extern __shared__ __align__(16) char dsm[];
    uint32_t aS = smem_u32(dsm);
    uint32_t bS = aS + (uint32_t)(2 * AROWS * ACOLS * 2);

    const int tid = threadIdx.x;
    const int warp = tid >> 5, lane = tid & 31;
    const int wm = warp % WM_, wn = warp / WM_;
    const int tr = lane & 7, tg = lane >> 3;

    auto load_tile = [&](int st, int kt) {
        {
            constexpr int CH = (OPA ? BM : BK) / 8;
            constexpr int TOT = AROWS * CH;
#pragma unroll
            for (int c0 = 0; c0 < TOT; c0 += 256) {
                int c = c0 + tid;
                int r = c / CH, s = (c % CH) * 8;
                const __half* src = OPA ? (Ab + (long long)(kt * BK + r) * lda + s)
                                        : (Ab + (long long)r * lda + kt * BK + s);
                cp16(aS + (uint32_t)(((st * AROWS + r) * ACOLS + s) * 2), src);
            }
        }
        {
            constexpr int CH = (OPB ? BK : BN) / 8;
            constexpr int TOT = BROWS * CH;
#pragma unroll
            for (int c0 = 0; c0 < TOT; c0 += 256) {
                int c = c0 + tid;
                int r = c / CH, s = (c % CH) * 8;
                const __half* src = OPB ? (Bb + (long long)r * ldb + kt * BK + s)
                                        : (Bb + (long long)(kt * BK + r) * ldb + s);
                cp16(bS + (uint32_t)(((st * BROWS + r) * BCOLS + s) * 2), src);
            }
        }
        cp_commit();
    };

    float acc[2][NF][4];
#pragma unroll
    for (int mi = 0; mi < 2; mi++)
#pragma unroll
        for (int ni = 0; ni < NF; ni++)
#pragma unroll
            for (int j = 0; j < 4; j++) acc[mi][ni][j] = 0.f;

    load_tile(0, 0);

    for (int kt = 0; kt < KT; kt++) {
        if (kt + 1 < KT) {
            load_tile((kt + 1) & 1, kt + 1);
            asm volatile("cp.async.wait_group 1;" ::: "memory");
        } else {
            asm volatile("cp.async.wait_group 0;" ::: "memory");
        }
        __syncthreads();

        const int st = kt & 1;
#pragma unroll
        for (int ks = 0; ks < KS; ks++) {
            const int k0 = ks * 16;
            uint32_t a[2][4];
#pragma unroll
            for (int mi = 0; mi < 2; mi++) {
                int r0 = wm * 32 + mi * 16;
                if (OPA == 0) {
                    int row = r0 + tr + (tg & 1) * 8, col = k0 + (tg >> 1) * 8;
                    ldm_x4(aS + (uint32_t)(((st * AROWS + row) * ACOLS + col) * 2),
                           a[mi][0], a[mi][1], a[mi][2], a[mi][3]);
                } else {
                    int row = k0 + tr + (tg >> 1) * 8, col = r0 + (tg & 1) * 8;
                    ldm_x4t(aS + (uint32_t)(((st * AROWS + row) * ACOLS + col) * 2),
                            a[mi][0], a[mi][1], a[mi][2], a[mi][3]);
                }
            }
            uint32_t b[NF][2];
#pragma unroll
            for (int np = 0; np < NF / 2; np++) {
                int c0 = wn * WNT + np * 16;
                uint32_t q0, q1, q2, q3;
                if (OPB == 0) {
                    int row = k0 + tr + (tg & 1) * 8, col = c0 + (tg >> 1) * 8;
                    ldm_x4t(bS + (uint32_t)(((st * BROWS + row) * BCOLS + col) * 2), q0, q1, q2, q3);
                } else {
                    int row = c0 + tr + (tg >> 1) * 8, col = k0 + (tg & 1) * 8;
                    ldm_x4(bS + (uint32_t)(((st * BROWS + row) * BCOLS + col) * 2), q0, q1, q2, q3);
                }
                b[np * 2][0] = q0; b[np * 2][1] = q1;
                b[np * 2 + 1][0] = q2; b[np * 2 + 1][1] = q3;
            }
#pragma unroll
            for (int mi = 0; mi < 2; mi++)
#pragma unroll
                for (int ni = 0; ni < NF; ni++)
                    mma16816(acc[mi][ni], a[mi], b[ni]);
        }
        __syncthreads();
    }

#pragma unroll
    for (int mi = 0; mi < 2; mi++) {
#pragma unroll
        for (int ni = 0; ni < NF; ni++) {
            int lr0 = wm * 32 + mi * 16 + (lane >> 2);
            int lc = wn * WNT + ni * 8 + (lane & 3) * 2;
            float* ac = acc[mi][ni];
#pragma unroll
            for (int hf = 0; hf < 2; hf++) {
                int r = lr0 + hf * 8;
                long long idx = (long long)(m_base + r) * 512 + n_base + lc;
                *reinterpret_cast<float2*>(Cf + idx) = make_float2(ac[hf * 2], ac[hf * 2 + 1]);
            }
        }
    }
}

// ---------------- combined energy kernel: z<16 = time NT, z>=16 = freq TN ----------------
__global__ __launch_bounds__(256) void k_energy_both()
{
    const int z = blockIdx.z;
    const int n_base = blockIdx.x * 128;
    const int m_base = blockIdx.y * 128;

    if (z < 16) {
        const int n = z & 3, kc = z >> 2;
        // time NT: A=qt[m][k] lda=4096, B=kt[n][k] ldb=4096
        const __half* Ab = g_qt + (long long)n * 2097152 + (long long)m_base * 4096 + kc * 1024;
        const __half* Bb = g_kt + (long long)n * 2097152 + (long long)n_base * 4096 + kc * 1024;
        float* Cf = g_E + (long long)kc * 1048576 + (long long)n * 262144;
        energy_body<128, 128, 64, 0, 1>(Ab, Bb, Cf, 4096, 4096, m_base, n_base);
    } else {
        const int zz = z - 16;
        const int n = zz & 3, kc = zz >> 2;
        // freq TN: A=qf[k][m] lda=512, B=kf[k][n] ldb=512
        const __half* Ab = g_qf + (long long)n * 2097152 + (long long)kc * 1024 * 512 + m_base;
        const __half* Bb = g_kf + (long long)n * 2097152 + (long long)kc * 1024 * 512 + n_base;
        float* Cf = g_Ef + (long long)kc * 1048576 + (long long)n * 262144;
        energy_body<128, 128, 64, 1, 0>(Ab, Bb, Cf, 512, 512, m_base, n_base);
    }
}

// ---------------- out GEMM (mma.sync, 2-stage — proven R2/R5 mainloop) ----------------
// OPA: 0 -> A[m][k], 1 -> A[k][m].   OPB: 0 -> B[k][n], 1 -> B[n][k].
// EPI: 6 tmp_half = 3*Xin + g*acc | 7 Cf = tmp_half + g*acc
// BMODE: 0 -> offA=z*bsA | 1 -> offA=(z>>6)*bsA
template<int BM, int BN, int BK, int OPA, int OPB, int EPI, int BMODE>
__global__ __launch_bounds__(256) void k_gemm(
    const __half* __restrict__ Ag, const __half* __restrict__ Bg,
    float* __restrict__ Cf, __half* __restrict__ Th,
    const float* __restrict__ gam, const float* __restrict__ Xin,
    int K, int lda, int ldb, int ldc,
    long long bsA, long long bsB, long long bsC)
{
    constexpr int WM_ = BM / 32;
    constexpr int WNT = BN / (8 / WM_);
    constexpr int NF = WNT / 8;
    constexpr int KS = BK / 16;
    constexpr int AROWS = OPA ? BK : BM;
    constexpr int ACOLS = (OPA ? BM : BK) + 8;
    constexpr int BROWS = OPB ? BN : BK;
    constexpr int BCOLS = (OPB ? BK : BN) + 8;

    extern __shared__ __align__(16) char dsm[];
    uint32_t aS = smem_u32(dsm);
    uint32_t bS = aS + (uint32_t)(2 * AROWS * ACOLS * 2);

    const int tid = threadIdx.x;
    const int warp = tid >> 5, lane = tid & 31;
    const int wm = warp % WM_, wn = warp / WM_;
    const int tr = lane & 7, tg = lane >> 3;

    const int z = blockIdx.z;
    const int n_base = blockIdx.x * BN;
    const int m_base = blockIdx.y * BM;

    long long offA = (BMODE == 1 ? (long long)(z >> 6) : (long long)z) * bsA;
    const __half* Ab = Ag + offA + (OPA ? (long long)m_base : (long long)m_base * lda);
    const __half* Bb = Bg + (long long)z * bsB + (OPB ? (long long)n_base * ldb : (long long)n_base);

    const int KT = K / BK;

    auto load_tile = [&](int st, int kt) {
        {
            constexpr int CH = (OPA ? BM : BK) / 8;
            constexpr int TOT = AROWS * CH;
#pragma unroll
            for (int c0 = 0; c0 < TOT; c0 += 256) {
                int c = c0 + tid;
                int r = c / CH, s = (c % CH) * 8;
                const __half* src = OPA ? (Ab + (long long)(kt * BK + r) * lda + s)
                                        : (Ab + (long long)r * lda + kt * BK + s);
                cp16(aS + (uint32_t)(((st * AROWS + r) * ACOLS + s) * 2), src);
            }
        }
        {
            constexpr int CH = (OPB ? BK : BN) / 8;
            constexpr int TOT = BROWS * CH;
#pragma unroll
            for (int c0 = 0; c0 < TOT; c0 += 256) {
                int c = c0 + tid;
                int r = c / CH, s = (c % CH) * 8;
                const __half* src = OPB ? (Bb + (long long)r * ldb + kt * BK + s)
                                        : (Bb + (long long)(kt * BK + r) * ldb + s);
                cp16(bS + (uint32_t)(((st * BROWS + r) * BCOLS + s) * 2), src);
            }
        }
        cp_commit();
    };

    float acc[2][NF][4];
#pragma unroll
    for (int mi = 0; mi < 2; mi++)
#pragma unroll
        for (int ni = 0; ni < NF; ni++)
#pragma unroll
            for (int j = 0; j < 4; j++) acc[mi][ni][j] = 0.f;

    load_tile(0, 0);

    for (int kt = 0; kt < KT; kt++) {
        if (kt + 1 < KT) {
            load_tile((kt + 1) & 1, kt + 1);
            asm volatile("cp.async.wait_group 1;" ::: "memory");
        } else {
            asm volatile("cp.async.wait_group 0;" ::: "memory");
        }
        __syncthreads();

        const int st = kt & 1;
#pragma unroll
        for (int ks = 0; ks < KS; ks++) {
            const int k0 = ks * 16;
            uint32_t a[2][4];
#pragma unroll
            for (int mi = 0; mi < 2; mi++) {
                int r0 = wm * 32 + mi * 16;
                if (OPA == 0) {
                    int row = r0 + tr + (tg & 1) * 8, col = k0 + (tg >> 1) * 8;
                    ldm_x4(aS + (uint32_t)(((st * AROWS + row) * ACOLS + col) * 2),
                           a[mi][0], a[mi][1], a[mi][2], a[mi][3]);
                } else {
                    int row = k0 + tr + (tg >> 1) * 8, col = r0 + (tg & 1) * 8;
                    ldm_x4t(aS + (uint32_t)(((st * AROWS + row) * ACOLS + col) * 2),
                            a[mi][0], a[mi][1], a[mi][2], a[mi][3]);
                }
            }
            uint32_t b[NF][2];
#pragma unroll
            for (int np = 0; np < NF / 2; np++) {
                int c0 = wn * WNT + np * 16;
                uint32_t q0, q1, q2, q3;
                if (OPB == 0) {
                    int row = k0 + tr + (tg & 1) * 8, col = c0 + (tg >> 1) * 8;
                    ldm_x4t(bS + (uint32_t)(((st * BROWS + row) * BCOLS + col) * 2), q0, q1, q2, q3);
                } else {
                    int row = c0 + tr + (tg >> 1) * 8, col = k0 + (tg & 1) * 8;
                    ldm_x4(bS + (uint32_t)(((st * BROWS + row) * BCOLS + col) * 2), q0, q1, q2, q3);
                }
                b[np * 2][0] = q0; b[np * 2][1] = q1;
                b[np * 2 + 1][0] = q2; b[np * 2 + 1][1] = q3;
            }
#pragma unroll
            for (int mi = 0; mi < 2; mi++)
#pragma unroll
                for (int ni = 0; ni < NF; ni++)
                    mma16816(acc[mi][ni], a[mi], b[ni]);
        }
        __syncthreads();
    }

    const float g = gam[0];
#pragma unroll
    for (int mi = 0; mi < 2; mi++) {
#pragma unroll
        for (int ni = 0; ni < NF; ni++) {
            int lr0 = wm * 32 + mi * 16 + (lane >> 2);
            int lc = wn * WNT + ni * 8 + (lane & 3) * 2;
            float* ac = acc[mi][ni];
#pragma unroll
            for (int hf = 0; hf < 2; hf++) {
                int r = lr0 + hf * 8;
                float v0 = ac[hf * 2 + 0], v1 = ac[hf * 2 + 1];
                long long idx = (long long)z * bsC + (long long)(m_base + r) * ldc + n_base + lc;
                if constexpr (EPI == 6) {
                    float2 xv = *reinterpret_cast<const float2*>(Xin + idx);
                    *reinterpret_cast<__half2*>(Th + idx) =
                        __floats2half2_rn(3.f * xv.x + g * v0, 3.f * xv.y + g * v1);
                } else {
                    __half2 tv = *reinterpret_cast<const __half2*>(Th + idx);
                    *reinterpret_cast<float2*>(Cf + idx) =
                        make_float2(__half2float(tv.x) + g * v0, __half2float(tv.y) + g * v1);
                }
            }
        }
    }
}

// ---------------- host launchers ----------------
template<int BM, int BN, int BK, int OPA, int OPB, int EPI, int BMODE>
static void launch_gemm(dim3 grid,
    const __half* A, const __half* B, float* Cf, __half* Th,
    const float* gam, const float* Xin,
    int K, int lda, int ldb, int ldc, long long bsA, long long bsB, long long bsC)
{
    constexpr int AR = OPA ? BK : BM, AC = (OPA ? BM : BK) + 8;
    constexpr int BR = OPB ? BN : BK, BC = (OPB ? BK : BN) + 8;
    constexpr int sz = 4 * (AR * AC + BR * BC);
    auto kfn = k_gemm<BM, BN, BK, OPA, OPB, EPI, BMODE>;
    cudaFuncSetAttribute(kfn, cudaFuncAttributeMaxDynamicSharedMemorySize, sz);
    kfn<<<grid, 256, sz>>>(A, B, Cf, Th, gam, Xin, K, lda, ldb, ldc, bsA, bsB, bsC);
}

extern "C" void kernel_launch(void* const* d_in, const int* in_sizes, int n_in,
                              void* d_out, int out_size)
{
    const float* x    = (const float*)d_in[0];
    const float* tq_w = (const float*)d_in[1];
    const float* tq_b = (const float*)d_in[2];
    const float* tk_w = (const float*)d_in[3];
    const float* tk_b = (const float*)d_in[4];
    const float* tv_w = (const float*)d_in[5];
    const float* tv_b = (const float*)d_in[6];
    const float* t_g  = (const float*)d_in[7];
    const float* fq_w = (const float*)d_in[8];
    const float* fq_b = (const float*)d_in[9];
    const float* fk_w = (const float*)d_in[10];
    const float* fk_b = (const float*)d_in[11];
    const float* fv_w = (const float*)d_in[12];
    const float* fv_b = (const float*)d_in[13];
    const float* f_g  = (const float*)d_in[14];
    float* out = (float*)d_out;

    __half *vt, *vf, *tmp, *attn;
    cudaGetSymbolAddress((void**)&vt, g_vt);
    cudaGetSymbolAddress((void**)&vf, g_vf);
    cudaGetSymbolAddress((void**)&tmp, g_tmp);
    cudaGetSymbolAddress((void**)&attn, g_attn);

    k_pack_w<<<1, 256>>>(tq_w, tk_w, fq_w, fk_w, tq_b, tk_b, fq_b, fk_b,
                         tv_w, fv_w, tv_b, fv_b);
    k_proj<<<8192, 256>>>(x);

    // combined energies (both passes, split-K=4, BN=128)
    {
        constexpr int sz = 4 * (128 * 72 + 128 * 72);   // time variant is larger
        cudaFuncSetAttribute(k_energy_both, cudaFuncAttributeMaxDynamicSharedMemorySize, sz);
        k_energy_both<<<dim3(4, 4, 32), 256, sz>>>();
    }
    // combined softmax (both passes)
    k_softmax_both<<<4096, 256>>>();

    // tmp = 3x + gt * attn_t@v   (fp16), batch z=(n,c)
    launch_gemm<128, 128, 64, 0, 0, 6, 1>(dim3(4, 4, 256),
        attn, vt, nullptr, tmp, t_g, x,
        512, 512, 512, 512, 262144LL, 262144LL, 262144LL);

    // out = tmp + gf * v@attn_f^T   (fp32), per n
    launch_gemm<128, 128, 64, 0, 1, 7, 0>(dim3(4, 256, 4),
        vf, attn + 1048576, out, tmp, f_g, nullptr,
        512, 512, 512, 512, 16777216LL, 262144LL, 16777216LL);
}

// round 11
// speedup vs baseline: 1.2025x; 1.0513x over previous
#include <cuda_runtime.h>
#include <cuda_fp16.h>
#include <cstdint>

// ---------------- static scratch ----------------
__device__ __half g_qt[8388608];       // time q  [n][h][c8][w]
__device__ __half g_kt[8388608];       // time k  [n][h][c8][w]
__device__ __half g_qf[8388608];       // freq q  [n][c8][h][w]
__device__ __half g_kf[8388608];       // freq k  [n][c8][h][w]
__device__ __half g_vt[67108864];      // time v  [n][c][g][w]   134 MB
__device__ __half g_vf[67108864];      // freq v  [n][c][h][w]   134 MB
__device__ float  g_E[4194304];        // time energy partials [4][n][512][512] 16 MB
__device__ float  g_Ef[4194304];       // freq energy partials [4][n][512][512] 16 MB
__device__ __half g_attn[2097152];     // gamma-prescaled attn: [0]=time, [1048576]=freq
__device__ __half g_wpack[10240];      // [160][64]: tq,tk,fq,fk,tv,fv
__device__ float  g_bpack[160];

// ---------------- helpers ----------------
__device__ __forceinline__ uint32_t smem_u32(const void* p) {
    return (uint32_t)__cvta_generic_to_shared(p);
}
__device__ __forceinline__ void cp16(uint32_t dst, const void* src) {
    asm volatile("cp.async.cg.shared.global [%0], [%1], 16;" :: "r"(dst), "l"(src));
}
__device__ __forceinline__ void cp_commit() {
    asm volatile("cp.async.commit_group;");
}
__device__ __forceinline__ void ldm_x4(uint32_t addr, uint32_t& r0, uint32_t& r1, uint32_t& r2, uint32_t& r3) {
    asm volatile("ldmatrix.sync.aligned.m8n8.x4.shared.b16 {%0,%1,%2,%3}, [%4];"
                 : "=r"(r0), "=r"(r1), "=r"(r2), "=r"(r3) : "r"(addr));
}
__device__ __forceinline__ void ldm_x4t(uint32_t addr, uint32_t& r0, uint32_t& r1, uint32_t& r2, uint32_t& r3) {
    asm volatile("ldmatrix.sync.aligned.m8n8.x4.trans.shared.b16 {%0,%1,%2,%3}, [%4];"
                 : "=r"(r0), "=r"(r1), "=r"(r2), "=r"(r3) : "r"(addr));
}
__device__ __forceinline__ void mma16816(float* c, const uint32_t* a, const uint32_t* b) {
    asm volatile("mma.sync.aligned.m16n8k16.row.col.f32.f16.f16.f32 "
                 "{%0,%1,%2,%3},{%4,%5,%6,%7},{%8,%9},{%0,%1,%2,%3};"
                 : "+f"(c[0]), "+f"(c[1]), "+f"(c[2]), "+f"(c[3])
                 : "r"(a[0]), "r"(a[1]), "r"(a[2]), "r"(a[3]), "r"(b[0]), "r"(b[1]));
}

// ---------------- weight packing ----------------
__global__ void k_pack_w(
    const float* __restrict__ tqw, const float* __restrict__ tkw,
    const float* __restrict__ fqw, const float* __restrict__ fkw,
    const float* __restrict__ tqb, const float* __restrict__ tkb,
    const float* __restrict__ fqb, const float* __restrict__ fkb,
    const float* __restrict__ tvw, const float* __restrict__ fvw,
    const float* __restrict__ tvb, const float* __restrict__ fvb)
{
    int t = threadIdx.x;
    for (int i = t; i < 512; i += 256) {
        g_wpack[i]        = __float2half(tqw[i]);
        g_wpack[512 + i]  = __float2half(tkw[i]);
        g_wpack[1024 + i] = __float2half(fqw[i]);
        g_wpack[1536 + i] = __float2half(fkw[i]);
    }
    for (int i = t; i < 4096; i += 256) {
        g_wpack[2048 + i] = __float2half(tvw[i]);
        g_wpack[6144 + i] = __float2half(fvw[i]);
    }
    if (t < 8) {
        g_bpack[t] = tqb[t]; g_bpack[8 + t] = tkb[t];
        g_bpack[16 + t] = fqb[t]; g_bpack[24 + t] = fkb[t];
    }
    if (t < 64) { g_bpack[32 + t] = tvb[t]; g_bpack[96 + t] = fvb[t]; }
}

// ---------------- fused projection (proven R5) ----------------
__global__ __launch_bounds__(256) void k_proj(const float* __restrict__ x)
{
    __shared__ __align__(16) __half Ws[160][72];
    __shared__ __align__(16) __half Xs[64][136];
    __shared__ float Bb[160];

    const int tid = threadIdx.x;
    const int warp = tid >> 5, lane = tid & 31;
    const int wm = warp >> 2, wn = warp & 3;
    const int tr = lane & 7, tg = lane >> 3;

    const int nb = blockIdx.x >> 11;
    const int chunk = blockIdx.x & 2047;
    const long long pix0 = (long long)chunk * 128;
    const int h = (int)(pix0 >> 9);
    const int w0 = (int)(pix0 & 511);

    uint32_t wS = smem_u32(&Ws[0][0]);
    for (int c = tid; c < 1280; c += 256) {
        int r = c >> 3, s = (c & 7) * 8;
        cp16(wS + (uint32_t)((r * 72 + s) * 2), g_wpack + r * 64 + s);
    }
    cp_commit();
    if (tid < 160) Bb[tid] = g_bpack[tid];

    const float4* x4 = reinterpret_cast<const float4*>(x) + (long long)nb * 4194304 + (pix0 >> 2);
    for (int i = tid; i < 2048; i += 256) {
        int c = i >> 5, f4 = i & 31;
        float4 f = x4[(long long)c * 65536 + f4];
        *reinterpret_cast<__half2*>(&Xs[c][f4 * 4])     = __floats2half2_rn(f.x, f.y);
        *reinterpret_cast<__half2*>(&Xs[c][f4 * 4 + 2]) = __floats2half2_rn(f.z, f.w);
    }
    asm volatile("cp.async.wait_group 0;" ::: "memory");
    __syncthreads();

    uint32_t xS = smem_u32(&Xs[0][0]);
    float acc[5][4][4];
#pragma unroll
    for (int mi = 0; mi < 5; mi++)
#pragma unroll
        for (int ni = 0; ni < 4; ni++)
#pragma unroll
            for (int j = 0; j < 4; j++) acc[mi][ni][j] = 0.f;

#pragma unroll
    for (int ks = 0; ks < 4; ks++) {
        const int k0 = ks * 16;
        uint32_t a[5][4];
#pragma unroll
        for (int mi = 0; mi < 5; mi++) {
            int row = wm * 80 + mi * 16 + tr + (tg & 1) * 8;
            int col = k0 + (tg >> 1) * 8;
            ldm_x4(wS + (uint32_t)((row * 72 + col) * 2), a[mi][0], a[mi][1], a[mi][2], a[mi][3]);
        }
        uint32_t b[4][2];
#pragma unroll
        for (int np = 0; np < 2; np++) {
            int row = k0 + tr + (tg & 1) * 8;
            int col = wn * 32 + np * 16 + (tg >> 1) * 8;
            uint32_t q0, q1, q2, q3;
            ldm_x4t(xS + (uint32_t)((row * 136 + col) * 2), q0, q1, q2, q3);
            b[np * 2][0] = q0; b[np * 2][1] = q1;
            b[np * 2 + 1][0] = q2; b[np * 2 + 1][1] = q3;
        }
#pragma unroll
        for (int mi = 0; mi < 5; mi++)
#pragma unroll
            for (int ni = 0; ni < 4; ni++)
                mma16816(acc[mi][ni], a[mi], b[ni]);
    }

#pragma unroll
    for (int mi = 0; mi < 5; mi++) {
#pragma unroll
        for (int ni = 0; ni < 4; ni++) {
            int lc = wn * 32 + ni * 8 + (lane & 3) * 2;
#pragma unroll
            for (int hf = 0; hf < 2; hf++) {
                int r = wm * 80 + mi * 16 + (lane >> 2) + hf * 8;
                float bv = Bb[r];
                __half2 hv = __floats2half2_rn(acc[mi][ni][hf * 2] + bv,
                                               acc[mi][ni][hf * 2 + 1] + bv);
                __half* dst;
                if (r < 32) {
                    int kind = r >> 3;
                    __half* base = kind == 0 ? g_qt : kind == 1 ? g_kt : kind == 2 ? g_qf : g_kf;
                    long long o = (long long)nb * 2097152;
                    if (kind < 2) dst = base + o + (long long)h * 4096 + (r & 7) * 512 + w0 + lc;
                    else          dst = base + o + (long long)(r & 7) * 262144 + pix0 + lc;
                } else {
                    int r2 = r - 32;
                    __half* base = (r2 < 64) ? g_vt : g_vf;
                    int cc = (r2 < 64) ? r2 : r2 - 64;
                    dst = base + (long long)nb * 16777216 + (long long)cc * 262144 + pix0 + lc;
                }
                *reinterpret_cast<__half2*>(dst) = hv;
            }
        }
    }
}

// ---------------- combined softmax, gamma-prescaled output ----------------
__global__ __launch_bounds__(256) void k_softmax_both(
    const float* __restrict__ tg, const float* __restrict__ fg)
{
    int r = blockIdx.x, t = threadIdx.x;
    int rr = r & 2047;
    const float* e = (r < 2048 ? g_E : g_Ef) + (long long)rr * 512;
    float v0 = e[t]       + e[t + 1048576]       + e[t + 2097152]       + e[t + 3145728];
    float v1 = e[t + 256] + e[t + 256 + 1048576] + e[t + 256 + 2097152] + e[t + 256 + 3145728];

    __shared__ float red[8];
    float m = fmaxf(v0, v1);
#pragma unroll
    for (int o = 16; o; o >>= 1) m = fmaxf(m, __shfl_xor_sync(0xffffffffu, m, o));
    if ((t & 31) == 0) red[t >> 5] = m;
    __syncthreads();
    float M = red[0];
#pragma unroll
    for (int i = 1; i < 8; i++) M = fmaxf(M, red[i]);
    __syncthreads();

    float e0 = __expf(v0 - M), e1 = __expf(v1 - M);
    float s = e0 + e1;
#pragma unroll
    for (int o = 16; o; o >>= 1) s += __shfl_xor_sync(0xffffffffu, s, o);
    if ((t & 31) == 0) red[t >> 5] = s;
    __syncthreads();
    float S = 0.f;
#pragma unroll
    for (int i = 0; i < 8; i++) S += red[i];
    float gmul = (r < 2048 ? tg[0] : fg[0]) / S;

    __half* a = g_attn + (r < 2048 ? 0 : 1048576) + (long long)rr * 512;
    a[t] = __float2half(e0 * gmul);
    a[t + 256] = __float2half(e1 * gmul);
}

// ---------------- energy GEMM body (proven R8) ----------------
template<int BM, int BN, int BK, int OPA, int OPB>
__device__ __forceinline__ void energy_body(
    const __half* __restrict__ Ab, const __half* __restrict__ Bb,
    float* __restrict__ Cf, int lda, int ldb, int m_base, int n_base)
{
    constexpr int WM_ = BM / 32;
    constexpr int WNT = BN / (8 / WM_);
    constexpr int NF = WNT / 8;
    constexpr int KS = BK / 16;
    constexpr int KT = 1024 / BK;
    constexpr int AROWS = OPA ? BK : BM;
    constexpr int ACOLS = (OPA ? BM : BK) + 8;
    constexpr int BROWS = OPB ? BN : BK;
    constexpr int BCOLS = (OPB ? BK : BN) + 8;

    extern __shared__ __align__(16) char dsm[];
    uint32_t aS = smem_u32(dsm);
    uint32_t bS = aS + (uint32_t)(2 * AROWS * ACOLS * 2);

    const int tid = threadIdx.x;
    const int warp = tid >> 5, lane = tid & 31;
    const int wm = warp % WM_, wn = warp / WM_;
    const int tr = lane & 7, tg = lane >> 3;

    auto load_tile = [&](int st, int kt) {
        {
            constexpr int CH = (OPA ? BM : BK) / 8;
            constexpr int TOT = AROWS * CH;
#pragma unroll
            for (int c0 = 0; c0 < TOT; c0 += 256) {
                int c = c0 + tid;
                int r = c / CH, s = (c % CH) * 8;
                const __half* src = OPA ? (Ab + (long long)(kt * BK + r) * lda + s)
                                        : (Ab + (long long)r * lda + kt * BK + s);
                cp16(aS + (uint32_t)(((st * AROWS + r) * ACOLS + s) * 2), src);
            }
        }
        {
            constexpr int CH = (OPB ? BK : BN) / 8;
            constexpr int TOT = BROWS * CH;
#pragma unroll
            for (int c0 = 0; c0 < TOT; c0 += 256) {
                int c = c0 + tid;
                int r = c / CH, s = (c % CH) * 8;
                const __half* src = OPB ? (Bb + (long long)r * ldb + kt * BK + s)
                                        : (Bb + (long long)(kt * BK + r) * ldb + s);
                cp16(bS + (uint32_t)(((st * BROWS + r) * BCOLS + s) * 2), src);
            }
        }
        cp_commit();
    };

    float acc[2][NF][4];
#pragma unroll
    for (int mi = 0; mi < 2; mi++)
#pragma unroll
        for (int ni = 0; ni < NF; ni++)
#pragma unroll
            for (int j = 0; j < 4; j++) acc[mi][ni][j] = 0.f;

    load_tile(0, 0);

    for (int kt = 0; kt < KT; kt++) {
        if (kt + 1 < KT) {
            load_tile((kt + 1) & 1, kt + 1);
            asm volatile("cp.async.wait_group 1;" ::: "memory");
        } else {
            asm volatile("cp.async.wait_group 0;" ::: "memory");
        }
        __syncthreads();

        const int st = kt & 1;
#pragma unroll
        for (int ks = 0; ks < KS; ks++) {
            const int k0 = ks * 16;
            uint32_t a[2][4];
#pragma unroll
            for (int mi = 0; mi < 2; mi++) {
                int r0 = wm * 32 + mi * 16;
                if (OPA == 0) {
                    int row = r0 + tr + (tg & 1) * 8, col = k0 + (tg >> 1) * 8;
                    ldm_x4(aS + (uint32_t)(((st * AROWS + row) * ACOLS + col) * 2),
                           a[mi][0], a[mi][1], a[mi][2], a[mi][3]);
                } else {
                    int row = k0 + tr + (tg >> 1) * 8, col = r0 + (tg & 1) * 8;
                    ldm_x4t(aS + (uint32_t)(((st * AROWS + row) * ACOLS + col) * 2),
                            a[mi][0], a[mi][1], a[mi][2], a[mi][3]);
                }
            }
            uint32_t b[NF][2];
#pragma unroll
            for (int np = 0; np < NF / 2; np++) {
                int c0 = wn * WNT + np * 16;
                uint32_t q0, q1, q2, q3;
                if (OPB == 0) {
                    int row = k0 + tr + (tg & 1) * 8, col = c0 + (tg >> 1) * 8;
                    ldm_x4t(bS + (uint32_t)(((st * BROWS + row) * BCOLS + col) * 2), q0, q1, q2, q3);
                } else {
                    int row = c0 + tr + (tg >> 1) * 8, col = k0 + (tg & 1) * 8;
                    ldm_x4(bS + (uint32_t)(((st * BROWS + row) * BCOLS + col) * 2), q0, q1, q2, q3);
                }
                b[np * 2][0] = q0; b[np * 2][1] = q1;
                b[np * 2 + 1][0] = q2; b[np * 2 + 1][1] = q3;
            }
#pragma unroll
            for (int mi = 0; mi < 2; mi++)
#pragma unroll
                for (int ni = 0; ni < NF; ni++)
                    mma16816(acc[mi][ni], a[mi], b[ni]);
        }
        __syncthreads();
    }

#pragma unroll
    for (int mi = 0; mi < 2; mi++) {
#pragma unroll
        for (int ni = 0; ni < NF; ni++) {
            int lr0 = wm * 32 + mi * 16 + (lane >> 2);
            int lc = wn * WNT + ni * 8 + (lane & 3) * 2;
            float* ac = acc[mi][ni];
#pragma unroll
            for (int hf = 0; hf < 2; hf++) {
                int r = lr0 + hf * 8;
                long long idx = (long long)(m_base + r) * 512 + n_base + lc;
                *reinterpret_cast<float2*>(Cf + idx) = make_float2(ac[hf * 2], ac[hf * 2 + 1]);
            }
        }
    }
}

// ---------------- combined energy kernel: z<16 = time NT, z>=16 = freq TN ----------------
__global__ __launch_bounds__(256) void k_energy_both()
{
    const int z = blockIdx.z;
    const int n_base = blockIdx.x * 128;
    const int m_base = blockIdx.y * 128;

    if (z < 16) {
        const int n = z & 3, kc = z >> 2;
        const __half* Ab = g_qt + (long long)n * 2097152 + (long long)m_base * 4096 + kc * 1024;
        const __half* Bb = g_kt + (long long)n * 2097152 + (long long)n_base * 4096 + kc * 1024;
        float* Cf = g_E + (long long)kc * 1048576 + (long long)n * 262144;
        energy_body<128, 128, 64, 0, 1>(Ab, Bb, Cf, 4096, 4096, m_base, n_base);
    } else {
        const int zz = z - 16;
        const int n = zz & 3, kc = zz >> 2;
        const __half* Ab = g_qf + (long long)n * 2097152 + (long long)kc * 1024 * 512 + m_base;
        const __half* Bb = g_kf + (long long)n * 2097152 + (long long)kc * 1024 * 512 + n_base;
        float* Cf = g_Ef + (long long)kc * 1048576 + (long long)n * 262144;
        energy_body<128, 128, 64, 1, 0>(Ab, Bb, Cf, 512, 512, m_base, n_base);
    }
}

// ---------------- fused dual out-GEMM ----------------
// Per (n,c) plane, one [128][128] output tile:
//   acc = attn_t'[h][g] @ vt[g][w]  (phase 0, kt 0..7, K=512)
//       + vf[h][v] @ attn_f'[w][v]^T (phase 1, kt 8..15, K=512)
//   out = 3*x + acc       (attn' pre-scaled by gamma in softmax)
__global__ __launch_bounds__(256) void k_out_fused(
    const float* __restrict__ x, float* __restrict__ out)
{
    constexpr int ACOLS = 72;
    constexpr int BC0 = 136;            // phase0 B: [64][136]
    constexpr int BC1 = 72;             // phase1 B: [128][72]
    constexpr int ASTRIDE = 128 * 72;   // halves per A stage
    constexpr int BSTRIDE = 128 * 72;   // halves per B stage (>= 64*136)

    extern __shared__ __align__(16) char dsm[];
    uint32_t aS = smem_u32(dsm);
    uint32_t bS = aS + (uint32_t)(2 * ASTRIDE * 2);

    const int tid = threadIdx.x;
    const int warp = tid >> 5, lane = tid & 31;
    const int wm = warp & 3, wn = warp >> 2;       // 4 x 2 warps
    const int tr = lane & 7, tg = lane >> 3;

    const int z = blockIdx.z;
    const int n = z >> 6, c = z & 63;
    const int n_base = blockIdx.x * 128;
    const int m_base = blockIdx.y * 128;

    const __half* At0 = g_attn + (long long)n * 262144 + (long long)m_base * 512;
    const __half* Bt0 = g_vt + (long long)n * 16777216 + (long long)c * 262144 + n_base;
    const __half* Af0 = g_vf + (long long)n * 16777216 + (long long)c * 262144 + (long long)m_base * 512;
    const __half* Bf0 = g_attn + 1048576 + (long long)n * 262144 + (long long)n_base * 512;

    auto load_tile = [&](int st, int kt) {
        if (kt < 8) {
            // A: attn_t' [128 m][64 k], lda=512
#pragma unroll
            for (int j = 0; j < 4; j++) {
                int i = tid + 256 * j;
                int r = i >> 3, s = (i & 7) * 8;
                cp16(aS + (uint32_t)((st * ASTRIDE + r * ACOLS + s) * 2),
                     At0 + (long long)r * 512 + kt * 64 + s);
            }
            // B: vt [64 k][128 n], ldb=512
#pragma unroll
            for (int j = 0; j < 4; j++) {
                int i = tid + 256 * j;
                int r = i >> 4, s = (i & 15) * 8;
                cp16(bS + (uint32_t)((st * BSTRIDE + r * BC0 + s) * 2),
                     Bt0 + (long long)(kt * 64 + r) * 512 + s);
            }
        } else {
            int k2 = kt - 8;
            // A: vf [128 m][64 k], lda=512
#pragma unroll
            for (int j = 0; j < 4; j++) {
                int i = tid + 256 * j;
                int r = i >> 3, s = (i & 7) * 8;
                cp16(aS + (uint32_t)((st * ASTRIDE + r * ACOLS + s) * 2),
                     Af0 + (long long)r * 512 + k2 * 64 + s);
            }
            // B: attn_f' [128 n][64 k], ldb=512
#pragma unroll
            for (int j = 0; j < 4; j++) {
                int i = tid + 256 * j;
                int r = i >> 3, s = (i & 7) * 8;
                cp16(bS + (uint32_t)((st * BSTRIDE + r * BC1 + s) * 2),
                     Bf0 + (long long)r * 512 + k2 * 64 + s);
            }
        }
        cp_commit();
    };

    float acc[2][8][4];
#pragma unroll
    for (int mi = 0; mi < 2; mi++)
#pragma unroll
        for (int ni = 0; ni < 8; ni++)
#pragma unroll
            for (int j = 0; j < 4; j++) acc[mi][ni][j] = 0.f;

    load_tile(0, 0);

    for (int kt = 0; kt < 16; kt++) {
        if (kt + 1 < 16) {
            load_tile((kt + 1) & 1, kt + 1);
            asm volatile("cp.async.wait_group 1;" ::: "memory");
        } else {
            asm volatile("cp.async.wait_group 0;" ::: "memory");
        }
        __syncthreads();

        const int st = kt & 1;
        const bool ph1 = (kt >= 8);
#pragma unroll
        for (int ks = 0; ks < 4; ks++) {
            const int k0 = ks * 16;
            uint32_t a[2][4];
#pragma unroll
            for (int mi = 0; mi < 2; mi++) {
                int row = wm * 32 + mi * 16 + tr + (tg & 1) * 8;
                int col = k0 + (tg >> 1) * 8;
                ldm_x4(aS + (uint32_t)((st * ASTRIDE + row * ACOLS + col) * 2),
                       a[mi][0], a[mi][1], a[mi][2], a[mi][3]);
            }
            uint32_t b[8][2];
#pragma unroll
            for (int np = 0; np < 4; np++) {
                int c0 = wn * 64 + np * 16;
                uint32_t q0, q1, q2, q3;
                if (!ph1) {
                    int row = k0 + tr + (tg & 1) * 8, col = c0 + (tg >> 1) * 8;
                    ldm_x4t(bS + (uint32_t)((st * BSTRIDE + row * BC0 + col) * 2), q0, q1, q2, q3);
                } else {
                    int row = c0 + tr + (tg >> 1) * 8, col = k0 + (tg & 1) * 8;
                    ldm_x4(bS + (uint32_t)((st * BSTRIDE + row * BC1 + col) * 2), q0, q1, q2, q3);
                }
                b[np * 2][0] = q0; b[np * 2][1] = q1;
                b[np * 2 + 1][0] = q2; b[np * 2 + 1][1] = q3;
            }
#pragma unroll
            for (int mi = 0; mi < 2; mi++)
#pragma unroll
                for (int ni = 0; ni < 8; ni++)
                    mma16816(acc[mi][ni], a[mi], b[ni]);
        }
        __syncthreads();
    }

    // epilogue: out = 3x + acc
#pragma unroll
    for (int mi = 0; mi < 2; mi++) {
#pragma unroll
        for (int ni = 0; ni < 8; ni++) {
            int lr0 = wm * 32 + mi * 16 + (lane >> 2);
            int lc = wn * 64 + ni * 8 + (lane & 3) * 2;
            float* ac = acc[mi][ni];
#pragma unroll
            for (int hf = 0; hf < 2; hf++) {
                int r = lr0 + hf * 8;
                long long idx = (long long)z * 262144 + (long long)(m_base + r) * 512 + n_base + lc;
                float2 xv = *reinterpret_cast<const float2*>(x + idx);
                *reinterpret_cast<float2*>(out + idx) =
                    make_float2(3.f * xv.x + ac[hf * 2], 3.f * xv.y + ac[hf * 2 + 1]);
            }
        }
    }
}

// ---------------- host ----------------
extern "C" void kernel_launch(void* const* d_in, const int* in_sizes, int n_in,
                              void* d_out, int out_size)
{
    const float* x    = (const float*)d_in[0];
    const float* tq_w = (const float*)d_in[1];
    const float* tq_b = (const float*)d_in[2];
    const float* tk_w = (const float*)d_in[3];
    const float* tk_b = (const float*)d_in[4];
    const float* tv_w = (const float*)d_in[5];
    const float* tv_b = (const float*)d_in[6];
    const float* t_g  = (const float*)d_in[7];
    const float* fq_w = (const float*)d_in[8];
    const float* fq_b = (const float*)d_in[9];
    const float* fk_w = (const float*)d_in[10];
    const float* fk_b = (const float*)d_in[11];
    const float* fv_w = (const float*)d_in[12];
    const float* fv_b = (const float*)d_in[13];
    const float* f_g  = (const float*)d_in[14];
    float* out = (float*)d_out;

    k_pack_w<<<1, 256>>>(tq_w, tk_w, fq_w, fk_w, tq_b, tk_b, fq_b, fk_b,
                         tv_w, fv_w, tv_b, fv_b);
    k_proj<<<8192, 256>>>(x);

    // combined energies (both passes, split-K=4, BN=128)
    {
        constexpr int sz = 4 * (128 * 72 + 128 * 72);
        cudaFuncSetAttribute(k_energy_both, cudaFuncAttributeMaxDynamicSharedMemorySize, sz);
        k_energy_both<<<dim3(4, 4, 32), 256, sz>>>();
    }
    // combined softmax (gamma-prescaled attn)
    k_softmax_both<<<4096, 256>>>(t_g, f_g);

    // fused dual out-GEMM: out = 3x + gt*attn_t@vt + gf*vf@attn_f^T
    {
        constexpr int sz = 2 * 2 * (128 * 72 + 128 * 72);   // 73728 B
        cudaFuncSetAttribute(k_out_fused, cudaFuncAttributeMaxDynamicSharedMemorySize, sz);
        k_out_fused<<<dim3(4, 4, 256), 256, sz>>>(x, out);
    }
}

// round 12
// speedup vs baseline: 1.3436x; 1.1174x over previous
#include <cuda_runtime.h>
#include <cuda_fp16.h>
#include <cstdint>

// ---------------- static scratch ----------------
__device__ __half g_qt[8388608];       // time q  [n][h][c8][w]
__device__ __half g_kt[8388608];       // time k  [n][h][c8][w]
__device__ __half g_qf[8388608];       // freq q  [n][c8][h][w]
__device__ __half g_kf[8388608];       // freq k  [n][c8][h][w]
__device__ __half g_vt[67108864];      // time v  [n][c][g][w]   134 MB
__device__ __half g_vf[67108864];      // freq v  [n][c][h][w]   134 MB
__device__ float  g_E[2097152];        // time energy partials [2][n][512][512] 8 MB
__device__ float  g_Ef[2097152];       // freq energy partials [2][n][512][512] 8 MB
__device__ __half g_attn[2097152];     // gamma-prescaled attn: [0]=time, [1048576]=freq
__device__ __half g_wpack[10240];      // [160][64]: tq,tk,fq,fk,tv,fv
__device__ float  g_bpack[160];

// ---------------- helpers ----------------
__device__ __forceinline__ uint32_t smem_u32(const void* p) {
    return (uint32_t)__cvta_generic_to_shared(p);
}
__device__ __forceinline__ void cp16(uint32_t dst, const void* src) {
    asm volatile("cp.async.cg.shared.global [%0], [%1], 16;" :: "r"(dst), "l"(src));
}
__device__ __forceinline__ void cp_commit() {
    asm volatile("cp.async.commit_group;");
}
__device__ __forceinline__ void ldm_x4(uint32_t addr, uint32_t& r0, uint32_t& r1, uint32_t& r2, uint32_t& r3) {
    asm volatile("ldmatrix.sync.aligned.m8n8.x4.shared.b16 {%0,%1,%2,%3}, [%4];"
                 : "=r"(r0), "=r"(r1), "=r"(r2), "=r"(r3) : "r"(addr));
}
__device__ __forceinline__ void ldm_x4t(uint32_t addr, uint32_t& r0, uint32_t& r1, uint32_t& r2, uint32_t& r3) {
    asm volatile("ldmatrix.sync.aligned.m8n8.x4.trans.shared.b16 {%0,%1,%2,%3}, [%4];"
                 : "=r"(r0), "=r"(r1), "=r"(r2), "=r"(r3) : "r"(addr));
}
__device__ __forceinline__ void mma16816(float* c, const uint32_t* a, const uint32_t* b) {
    asm volatile("mma.sync.aligned.m16n8k16.row.col.f32.f16.f16.f32 "
                 "{%0,%1,%2,%3},{%4,%5,%6,%7},{%8,%9},{%0,%1,%2,%3};"
                 : "+f"(c[0]), "+f"(c[1]), "+f"(c[2]), "+f"(c[3])
                 : "r"(a[0]), "r"(a[1]), "r"(a[2]), "r"(a[3]), "r"(b[0]), "r"(b[1]));
}

// ---------------- weight packing ----------------
__global__ void k_pack_w(
    const float* __restrict__ tqw, const float* __restrict__ tkw,
    const float* __restrict__ fqw, const float* __restrict__ fkw,
    const float* __restrict__ tqb, const float* __restrict__ tkb,
    const float* __restrict__ fqb, const float* __restrict__ fkb,
    const float* __restrict__ tvw, const float* __restrict__ fvw,
    const float* __restrict__ tvb, const float* __restrict__ fvb)
{
    int t = threadIdx.x;
    for (int i = t; i < 512; i += 256) {
        g_wpack[i]        = __float2half(tqw[i]);
        g_wpack[512 + i]  = __float2half(tkw[i]);
        g_wpack[1024 + i] = __float2half(fqw[i]);
        g_wpack[1536 + i] = __float2half(fkw[i]);
    }
    for (int i = t; i < 4096; i += 256) {
        g_wpack[2048 + i] = __float2half(tvw[i]);
        g_wpack[6144 + i] = __float2half(fvw[i]);
    }
    if (t < 8) {
        g_bpack[t] = tqb[t]; g_bpack[8 + t] = tkb[t];
        g_bpack[16 + t] = fqb[t]; g_bpack[24 + t] = fkb[t];
    }
    if (t < 64) { g_bpack[32 + t] = tvb[t]; g_bpack[96 + t] = fvb[t]; }
}

// ---------------- fused projection (cp.async staged x) ----------------
__global__ __launch_bounds__(256) void k_proj(const float* __restrict__ x)
{
    __shared__ __align__(16) __half Ws[160][72];
    __shared__ __align__(16) __half Xs[64][136];
    __shared__ __align__(16) float4 XsF[64][33];   // fp32 staging for x tile
    __shared__ float Bb[160];

    const int tid = threadIdx.x;
    const int warp = tid >> 5, lane = tid & 31;
    const int wm = warp >> 2, wn = warp & 3;
    const int tr = lane & 7, tg = lane >> 3;

    const int nb = blockIdx.x >> 11;
    const int chunk = blockIdx.x & 2047;
    const long long pix0 = (long long)chunk * 128;
    const int h = (int)(pix0 >> 9);
    const int w0 = (int)(pix0 & 511);

    // weights via cp.async
    uint32_t wS = smem_u32(&Ws[0][0]);
    for (int c = tid; c < 1280; c += 256) {
        int r = c >> 3, s = (c & 7) * 8;
        cp16(wS + (uint32_t)((r * 72 + s) * 2), g_wpack + r * 64 + s);
    }
    // x tile via cp.async into fp32 staging: 64 channels x 32 float4
    uint32_t fS = smem_u32(&XsF[0][0]);
    const float4* x4 = reinterpret_cast<const float4*>(x) + (long long)nb * 4194304 + (pix0 >> 2);
    for (int i = tid; i < 2048; i += 256) {
        int c = i >> 5, f4 = i & 31;
        cp16(fS + (uint32_t)((c * 33 + f4) * 16), x4 + (long long)c * 65536 + f4);
    }
    cp_commit();
    if (tid < 160) Bb[tid] = g_bpack[tid];

    asm volatile("cp.async.wait_group 0;" ::: "memory");
    __syncthreads();

    // convert staged fp32 -> fp16 Xs
    for (int i = tid; i < 2048; i += 256) {
        int c = i >> 5, f4 = i & 31;
        float4 f = XsF[c][f4];
        *reinterpret_cast<__half2*>(&Xs[c][f4 * 4])     = __floats2half2_rn(f.x, f.y);
        *reinterpret_cast<__half2*>(&Xs[c][f4 * 4 + 2]) = __floats2half2_rn(f.z, f.w);
    }
    __syncthreads();

    uint32_t xS = smem_u32(&Xs[0][0]);
    float acc[5][4][4];
#pragma unroll
    for (int mi = 0; mi < 5; mi++)
#pragma unroll
        for (int ni = 0; ni < 4; ni++)
#pragma unroll
            for (int j = 0; j < 4; j++) acc[mi][ni][j] = 0.f;

#pragma unroll
    for (int ks = 0; ks < 4; ks++) {
        const int k0 = ks * 16;
        uint32_t a[5][4];
#pragma unroll
        for (int mi = 0; mi < 5; mi++) {
            int row = wm * 80 + mi * 16 + tr + (tg & 1) * 8;
            int col = k0 + (tg >> 1) * 8;
            ldm_x4(wS + (uint32_t)((row * 72 + col) * 2), a[mi][0], a[mi][1], a[mi][2], a[mi][3]);
        }
        uint32_t b[4][2];
#pragma unroll
        for (int np = 0; np < 2; np++) {
            int row = k0 + tr + (tg & 1) * 8;
            int col = wn * 32 + np * 16 + (tg >> 1) * 8;
            uint32_t q0, q1, q2, q3;
            ldm_x4t(xS + (uint32_t)((row * 136 + col) * 2), q0, q1, q2, q3);
            b[np * 2][0] = q0; b[np * 2][1] = q1;
            b[np * 2 + 1][0] = q2; b[np * 2 + 1][1] = q3;
        }
#pragma unroll
        for (int mi = 0; mi < 5; mi++)
#pragma unroll
            for (int ni = 0; ni < 4; ni++)
                mma16816(acc[mi][ni], a[mi], b[ni]);
    }

#pragma unroll
    for (int mi = 0; mi < 5; mi++) {
#pragma unroll
        for (int ni = 0; ni < 4; ni++) {
            int lc = wn * 32 + ni * 8 + (lane & 3) * 2;
#pragma unroll
            for (int hf = 0; hf < 2; hf++) {
                int r = wm * 80 + mi * 16 + (lane >> 2) + hf * 8;
                float bv = Bb[r];
                __half2 hv = __floats2half2_rn(acc[mi][ni][hf * 2] + bv,
                                               acc[mi][ni][hf * 2 + 1] + bv);
                __half* dst;
                if (r < 32) {
                    int kind = r >> 3;
                    __half* base = kind == 0 ? g_qt : kind == 1 ? g_kt : kind == 2 ? g_qf : g_kf;
                    long long o = (long long)nb * 2097152;
                    if (kind < 2) dst = base + o + (long long)h * 4096 + (r & 7) * 512 + w0 + lc;
                    else          dst = base + o + (long long)(r & 7) * 262144 + pix0 + lc;
                } else {
                    int r2 = r - 32;
                    __half* base = (r2 < 64) ? g_vt : g_vf;
                    int cc = (r2 < 64) ? r2 : r2 - 64;
                    dst = base + (long long)nb * 16777216 + (long long)cc * 262144 + pix0 + lc;
                }
                *reinterpret_cast<__half2*>(dst) = hv;
            }
        }
    }
}

// ---------------- combined softmax (split-K=2), gamma-prescaled output ----------------
__global__ __launch_bounds__(256) void k_softmax_both(
    const float* __restrict__ tg, const float* __restrict__ fg)
{
    int r = blockIdx.x, t = threadIdx.x;
    int rr = r & 2047;
    const float* e = (r < 2048 ? g_E : g_Ef) + (long long)rr * 512;
    float v0 = e[t]       + e[t + 1048576];
    float v1 = e[t + 256] + e[t + 256 + 1048576];

    __shared__ float red[8];
    float m = fmaxf(v0, v1);
#pragma unroll
    for (int o = 16; o; o >>= 1) m = fmaxf(m, __shfl_xor_sync(0xffffffffu, m, o));
    if ((t & 31) == 0) red[t >> 5] = m;
    __syncthreads();
    float M = red[0];
#pragma unroll
    for (int i = 1; i < 8; i++) M = fmaxf(M, red[i]);
    __syncthreads();

    float e0 = __expf(v0 - M), e1 = __expf(v1 - M);
    float s = e0 + e1;
#pragma unroll
    for (int o = 16; o; o >>= 1) s += __shfl_xor_sync(0xffffffffu, s, o);
    if ((t & 31) == 0) red[t >> 5] = s;
    __syncthreads();
    float S = 0.f;
#pragma unroll
    for (int i = 0; i < 8; i++) S += red[i];
    float gmul = (r < 2048 ? tg[0] : fg[0]) / S;

    __half* a = g_attn + (r < 2048 ? 0 : 1048576) + (long long)rr * 512;
    a[t] = __float2half(e0 * gmul);
    a[t + 256] = __float2half(e1 * gmul);
}

// ---------------- energy GEMM body (K=2048 per CTA) ----------------
template<int BM, int BN, int BK, int OPA, int OPB>
__device__ __forceinline__ void energy_body(
    const __half* __restrict__ Ab, const __half* __restrict__ Bb,
    float* __restrict__ Cf, int lda, int ldb, int m_base, int n_base)
{
    constexpr int WM_ = BM / 32;
    constexpr int WNT = BN / (8 / WM_);
    constexpr int NF = WNT / 8;
    constexpr int KS = BK / 16;
    constexpr int KT = 2048 / BK;
    constexpr int AROWS = OPA ? BK : BM;
    constexpr int ACOLS = (OPA ? BM : BK) + 8;
    constexpr int BROWS = OPB ? BN : BK;
    constexpr int BCOLS = (OPB ? BK : BN) + 8;

    extern __shared__ __align__(16) char dsm[];
    uint32_t aS = smem_u32(dsm);
    uint32_t bS = aS + (uint32_t)(2 * AROWS * ACOLS * 2);

    const int tid = threadIdx.x;
    const int warp = tid >> 5, lane = tid & 31;
    const int wm = warp % WM_, wn = warp / WM_;
    const int tr = lane & 7, tg = lane >> 3;

    auto load_tile = [&](int st, int kt) {
        {
            constexpr int CH = (OPA ? BM : BK) / 8;
            constexpr int TOT = AROWS * CH;
#pragma unroll
            for (int c0 = 0; c0 < TOT; c0 += 256) {
                int c = c0 + tid;
                int r = c / CH, s = (c % CH) * 8;
                const __half* src = OPA ? (Ab + (long long)(kt * BK + r) * lda + s)
                                        : (Ab + (long long)r * lda + kt * BK + s);
                cp16(aS + (uint32_t)(((st * AROWS + r) * ACOLS + s) * 2), src);
            }
        }
        {
            constexpr int CH = (OPB ? BK : BN) / 8;
            constexpr int TOT = BROWS * CH;
#pragma unroll
            for (int c0 = 0; c0 < TOT; c0 += 256) {
                int c = c0 + tid;
                int r = c / CH, s = (c % CH) * 8;
                const __half* src = OPB ? (Bb + (long long)r * ldb + kt * BK + s)
                                        : (Bb + (long long)(kt * BK + r) * ldb + s);
                cp16(bS + (uint32_t)(((st * BROWS + r) * BCOLS + s) * 2), src);
            }
        }
        cp_commit();
    };

    float acc[2][NF][4];
#pragma unroll
    for (int mi = 0; mi < 2; mi++)
#pragma unroll
        for (int ni = 0; ni < NF; ni++)
#pragma unroll
            for (int j = 0; j < 4; j++) acc[mi][ni][j] = 0.f;

    load_tile(0, 0);

    for (int kt = 0; kt < KT; kt++) {
        if (kt + 1 < KT) {
            load_tile((kt + 1) & 1, kt + 1);
            asm volatile("cp.async.wait_group 1;" ::: "memory");
        } else {
            asm volatile("cp.async.wait_group 0;" ::: "memory");
        }
        __syncthreads();

        const int st = kt & 1;
#pragma unroll
        for (int ks = 0; ks < KS; ks++) {
            const int k0 = ks * 16;
            uint32_t a[2][4];
#pragma unroll
            for (int mi = 0; mi < 2; mi++) {
                int r0 = wm * 32 + mi * 16;
                if (OPA == 0) {
                    int row = r0 + tr + (tg & 1) * 8, col = k0 + (tg >> 1) * 8;
                    ldm_x4(aS + (uint32_t)(((st * AROWS + row) * ACOLS + col) * 2),
                           a[mi][0], a[mi][1], a[mi][2], a[mi][3]);
                } else {
                    int row = k0 + tr + (tg >> 1) * 8, col = r0 + (tg & 1) * 8;
                    ldm_x4t(aS + (uint32_t)(((st * AROWS + row) * ACOLS + col) * 2),
                            a[mi][0], a[mi][1], a[mi][2], a[mi][3]);
                }
            }
            uint32_t b[NF][2];
#pragma unroll
            for (int np = 0; np < NF / 2; np++) {
                int c0 = wn * WNT + np * 16;
                uint32_t q0, q1, q2, q3;
                if (OPB == 0) {
                    int row = k0 + tr + (tg & 1) * 8, col = c0 + (tg >> 1) * 8;
                    ldm_x4t(bS + (uint32_t)(((st * BROWS + row) * BCOLS + col) * 2), q0, q1, q2, q3);
                } else {
                    int row = c0 + tr + (tg >> 1) * 8, col = k0 + (tg & 1) * 8;
                    ldm_x4(bS + (uint32_t)(((st * BROWS + row) * BCOLS + col) * 2), q0, q1, q2, q3);
                }
                b[np * 2][0] = q0; b[np * 2][1] = q1;
                b[np * 2 + 1][0] = q2; b[np * 2 + 1][1] = q3;
            }
#pragma unroll
            for (int mi = 0; mi < 2; mi++)
#pragma unroll
                for (int ni = 0; ni < NF; ni++)
                    mma16816(acc[mi][ni], a[mi], b[ni]);
        }
        __syncthreads();
    }

#pragma unroll
    for (int mi = 0; mi < 2; mi++) {
#pragma unroll
        for (int ni = 0; ni < NF; ni++) {
            int lr0 = wm * 32 + mi * 16 + (lane >> 2);
            int lc = wn * WNT + ni * 8 + (lane & 3) * 2;
            float* ac = acc[mi][ni];
#pragma unroll
            for (int hf = 0; hf < 2; hf++) {
                int r = lr0 + hf * 8;
                long long idx = (long long)(m_base + r) * 512 + n_base + lc;
                *reinterpret_cast<float2*>(Cf + idx) = make_float2(ac[hf * 2], ac[hf * 2 + 1]);
            }
        }
    }
}

// ---------------- combined energy kernel: z<8 = time NT, z>=8 = freq TN (split-K=2) ----------------
__global__ __launch_bounds__(256) void k_energy_both()
{
    const int z = blockIdx.z;
    const int n_base = blockIdx.x * 128;
    const int m_base = blockIdx.y * 128;

    if (z < 8) {
        const int n = z & 3, kc = z >> 2;
        const __half* Ab = g_qt + (long long)n * 2097152 + (long long)m_base * 4096 + kc * 2048;
        const __half* Bb = g_kt + (long long)n * 2097152 + (long long)n_base * 4096 + kc * 2048;
        float* Cf = g_E + (long long)kc * 1048576 + (long long)n * 262144;
        energy_body<128, 128, 64, 0, 1>(Ab, Bb, Cf, 4096, 4096, m_base, n_base);
    } else {
        const int zz = z - 8;
        const int n = zz & 3, kc = zz >> 2;
        const __half* Ab = g_qf + (long long)n * 2097152 + (long long)kc * 2048 * 512 + m_base;
        const __half* Bb = g_kf + (long long)n * 2097152 + (long long)kc * 2048 * 512 + n_base;
        float* Cf = g_Ef + (long long)kc * 1048576 + (long long)n * 262144;
        energy_body<128, 128, 64, 1, 0>(Ab, Bb, Cf, 512, 512, m_base, n_base);
    }
}

// ---------------- fused dual out-GEMM (proven R11) ----------------
__global__ __launch_bounds__(256) void k_out_fused(
    const float* __restrict__ x, float* __restrict__ out)
{
    constexpr int ACOLS = 72;
    constexpr int BC0 = 136;
    constexpr int BC1 = 72;
    constexpr int ASTRIDE = 128 * 72;
    constexpr int BSTRIDE = 128 * 72;

    extern __shared__ __align__(16) char dsm[];
    uint32_t aS = smem_u32(dsm);
    uint32_t bS = aS + (uint32_t)(2 * ASTRIDE * 2);

    const int tid = threadIdx.x;
    const int warp = tid >> 5, lane = tid & 31;
    const int wm = warp & 3, wn = warp >> 2;
    const int tr = lane & 7, tg = lane >> 3;

    const int z = blockIdx.z;
    const int n = z >> 6, c = z & 63;
    const int n_base = blockIdx.x * 128;
    const int m_base = blockIdx.y * 128;

    const __half* At0 = g_attn + (long long)n * 262144 + (long long)m_base * 512;
    const __half* Bt0 = g_vt + (long long)n * 16777216 + (long long)c * 262144 + n_base;
    const __half* Af0 = g_vf + (long long)n * 16777216 + (long long)c * 262144 + (long long)m_base * 512;
    const __half* Bf0 = g_attn + 1048576 + (long long)n * 262144 + (long long)n_base * 512;

    auto load_tile = [&](int st, int kt) {
        if (kt < 8) {
#pragma unroll
            for (int j = 0; j < 4; j++) {
                int i = tid + 256 * j;
                int r = i >> 3, s = (i & 7) * 8;
                cp16(aS + (uint32_t)((st * ASTRIDE + r * ACOLS + s) * 2),
                     At0 + (long long)r * 512 + kt * 64 + s);
            }
#pragma unroll
            for (int j = 0; j < 4; j++) {
                int i = tid + 256 * j;
                int r = i >> 4, s = (i & 15) * 8;
                cp16(bS + (uint32_t)((st * BSTRIDE + r * BC0 + s) * 2),
                     Bt0 + (long long)(kt * 64 + r) * 512 + s);
            }
        } else {
            int k2 = kt - 8;
#pragma unroll
            for (int j = 0; j < 4; j++) {
                int i = tid + 256 * j;
                int r = i >> 3, s = (i & 7) * 8;
                cp16(aS + (uint32_t)((st * ASTRIDE + r * ACOLS + s) * 2),
                     Af0 + (long long)r * 512 + k2 * 64 + s);
            }
#pragma unroll
            for (int j = 0; j < 4; j++) {
                int i = tid + 256 * j;
                int r = i >> 3, s = (i & 7) * 8;
                cp16(bS + (uint32_t)((st * BSTRIDE + r * BC1 + s) * 2),
                     Bf0 + (long long)r * 512 + k2 * 64 + s);
            }
        }
        cp_commit();
    };

    float acc[2][8][4];
#pragma unroll
    for (int mi = 0; mi < 2; mi++)
#pragma unroll
        for (int ni = 0; ni < 8; ni++)
#pragma unroll
            for (int j = 0; j < 4; j++) acc[mi][ni][j] = 0.f;

    load_tile(0, 0);

    for (int kt = 0; kt < 16; kt++) {
        if (kt + 1 < 16) {
            load_tile((kt + 1) & 1, kt + 1);
            asm volatile("cp.async.wait_group 1;" ::: "memory");
        } else {
            asm volatile("cp.async.wait_group 0;" ::: "memory");
        }
        __syncthreads();

        const int st = kt & 1;
        const bool ph1 = (kt >= 8);
#pragma unroll
        for (int ks = 0; ks < 4; ks++) {
            const int k0 = ks * 16;
            uint32_t a[2][4];
#pragma unroll
            for (int mi = 0; mi < 2; mi++) {
                int row = wm * 32 + mi * 16 + tr + (tg & 1) * 8;
                int col = k0 + (tg >> 1) * 8;
                ldm_x4(aS + (uint32_t)((st * ASTRIDE + row * ACOLS + col) * 2),
                       a[mi][0], a[mi][1], a[mi][2], a[mi][3]);
            }
            uint32_t b[8][2];
#pragma unroll
            for (int np = 0; np < 4; np++) {
                int c0 = wn * 64 + np * 16;
                uint32_t q0, q1, q2, q3;
                if (!ph1) {
                    int row = k0 + tr + (tg & 1) * 8, col = c0 + (tg >> 1) * 8;
                    ldm_x4t(bS + (uint32_t)((st * BSTRIDE + row * BC0 + col) * 2), q0, q1, q2, q3);
                } else {
                    int row = c0 + tr + (tg >> 1) * 8, col = k0 + (tg & 1) * 8;
                    ldm_x4(bS + (uint32_t)((st * BSTRIDE + row * BC1 + col) * 2), q0, q1, q2, q3);
                }
                b[np * 2][0] = q0; b[np * 2][1] = q1;
                b[np * 2 + 1][0] = q2; b[np * 2 + 1][1] = q3;
            }
#pragma unroll
            for (int mi = 0; mi < 2; mi++)
#pragma unroll
                for (int ni = 0; ni < 8; ni++)
                    mma16816(acc[mi][ni], a[mi], b[ni]);
        }
        __syncthreads();
    }

#pragma unroll
    for (int mi = 0; mi < 2; mi++) {
#pragma unroll
        for (int ni = 0; ni < 8; ni++) {
            int lr0 = wm * 32 + mi * 16 + (lane >> 2);
            int lc = wn * 64 + ni * 8 + (lane & 3) * 2;
            float* ac = acc[mi][ni];
#pragma unroll
            for (int hf = 0; hf < 2; hf++) {
                int r = lr0 + hf * 8;
                long long idx = (long long)z * 262144 + (long long)(m_base + r) * 512 + n_base + lc;
                float2 xv = *reinterpret_cast<const float2*>(x + idx);
                *reinterpret_cast<float2*>(out + idx) =
                    make_float2(3.f * xv.x + ac[hf * 2], 3.f * xv.y + ac[hf * 2 + 1]);
            }
        }
    }
}

// ---------------- host ----------------
extern "C" void kernel_launch(void* const* d_in, const int* in_sizes, int n_in,
                              void* d_out, int out_size)
{
    const float* x    = (const float*)d_in[0];
    const float* tq_w = (const float*)d_in[1];
    const float* tq_b = (const float*)d_in[2];
    const float* tk_w = (const float*)d_in[3];
    const float* tk_b = (const float*)d_in[4];
    const float* tv_w = (const float*)d_in[5];
    const float* tv_b = (const float*)d_in[6];
    const float* t_g  = (const float*)d_in[7];
    const float* fq_w = (const float*)d_in[8];
    const float* fq_b = (const float*)d_in[9];
    const float* fk_w = (const float*)d_in[10];
    const float* fk_b = (const float*)d_in[11];
    const float* fv_w = (const float*)d_in[12];
    const float* fv_b = (const float*)d_in[13];
    const float* f_g  = (const float*)d_in[14];
    float* out = (float*)d_out;

    k_pack_w<<<1, 256>>>(tq_w, tk_w, fq_w, fk_w, tq_b, tk_b, fq_b, fk_b,
                         tv_w, fv_w, tv_b, fv_b);
    k_proj<<<8192, 256>>>(x);

    // combined energies (both passes, split-K=2, BN=128): 256 CTAs
    {
        constexpr int sz = 4 * (128 * 72 + 128 * 72);
        cudaFuncSetAttribute(k_energy_both, cudaFuncAttributeMaxDynamicSharedMemorySize, sz);
        k_energy_both<<<dim3(4, 4, 16), 256, sz>>>();
    }
    // combined softmax (gamma-prescaled attn)
    k_softmax_both<<<4096, 256>>>(t_g, f_g);

    // fused dual out-GEMM: out = 3x + gt*attn_t@vt + gf*vf@attn_f^T
    {
        constexpr int sz = 2 * 2 * (128 * 72 + 128 * 72);   // 73728 B
        cudaFuncSetAttribute(k_out_fused, cudaFuncAttributeMaxDynamicSharedMemorySize, sz);
        k_out_fused<<<dim3(4, 4, 256), 256, sz>>>(x, out);
    }
}